// round 7
// baseline (speedup 1.0000x reference)
#include <cuda_runtime.h>
#include <cstdint>
#include <math.h>

#define TGT   2048
#define NBSZ  2
#define EMB   1024
#define NH    16
#define HD    64
#define NBH   (NBSZ*NH)      // 32
#define MROWS (TGT*NBSZ)     // 4096

// ---------------- scratch (device globals) ---------------------------------
static __device__ float  g_Q  [(size_t)NBH*TGT*HD];     // pre-rounded tf32
static __device__ float  g_K  [(size_t)NBH*TGT*HD];     // pre-rounded tf32
static __device__ float  g_Vt [(size_t)NBH*HD*TGT];     // pre-rounded tf32
static __device__ float  g_attn[(size_t)MROWS*EMB];     // pre-rounded tf32
static __device__ float2 g_stats[(size_t)NBH*TGT];      // (rowmax, 1/rowsum)
static __device__ float  g_qc [(size_t)MROWS*EMB];      // query, tf32
static __device__ float  g_wic[(size_t)3*EMB*EMB];      // in_proj_w, tf32
static __device__ float  g_woc[(size_t)EMB*EMB];        // out_w, tf32

// ---------------- helpers ---------------------------------------------------
__device__ __forceinline__ uint32_t f2tf32(float x){
    uint32_t u; asm("cvt.rna.tf32.f32 %0, %1;" : "=r"(u) : "f"(x)); return u;
}
__device__ __forceinline__ float rt(float x){ return __uint_as_float(f2tf32(x)); }
__device__ __forceinline__ float4 tf4(float4 v){
    v.x = rt(v.x); v.y = rt(v.y); v.z = rt(v.z); v.w = rt(v.w); return v;
}
__device__ __forceinline__ void mma8(float* c, const uint32_t* a, const uint32_t* b){
    asm volatile("mma.sync.aligned.m16n8k8.row.col.f32.tf32.tf32.f32 "
        "{%0,%1,%2,%3}, {%4,%5,%6,%7}, {%8,%9}, {%0,%1,%2,%3};"
        : "+f"(c[0]), "+f"(c[1]), "+f"(c[2]), "+f"(c[3])
        : "r"(a[0]), "r"(a[1]), "r"(a[2]), "r"(a[3]), "r"(b[0]), "r"(b[1]));
}
__device__ __forceinline__ uint32_t smem_u32(const void* p){
    uint32_t a; asm("{ .reg .u64 t; cvta.to.shared.u64 t, %1; cvt.u32.u64 %0, t; }":"=r"(a):"l"(p));
    return a;
}
__device__ __forceinline__ void cpa16(uint32_t s, const void* g){
    asm volatile("cp.async.cg.shared.global [%0], [%1], 16;" :: "r"(s), "l"(g) : "memory");
}
#define CP_COMMIT() asm volatile("cp.async.commit_group;" ::: "memory")
#define CP_WAIT(n)  asm volatile("cp.async.wait_group %0;" :: "n"(n) : "memory")

// ---------------- pre-round inputs to tf32 ----------------------------------
__global__ void preround_k(const float4* __restrict__ src, float4* __restrict__ dst, int n4)
{
    int i = blockIdx.x*blockDim.x + threadIdx.x;
    if (i < n4) dst[i] = tf4(src[i]);
}

// ===========================================================================
// Projection GEMMs: block 256(M)x128(N), 256 thr, warp tile 64x64.
// 3-stage cp.async ring, ONE syncthreads per k-chunk.
// SMEM floats: A stage i @ i*9216 (256x36), B stage i @ 27648+i*4608 (128x36)
//   total 41472 floats = 165888 B
// ===========================================================================
#define GEMM_SMEM_BYTES (41472*4)

template<int MODE>
__global__ __launch_bounds__(256)
void mma_gemm(float* __restrict__ Cg, const float* __restrict__ biasg)
{
    constexpr int KC = 32;
    extern __shared__ float sm[];
    const uint32_t sb = smem_u32(sm);
    const int tid = threadIdx.x, lane = tid & 31, wid = tid >> 5;
    const int wm = wid & 3, wn = wid >> 2;          // 4(m) x 2(n)
    const int lr = lane >> 2, lc = lane & 3;
    const int bm = blockIdx.y * 256, bn = blockIdx.x * 128;

    const float* A = (MODE == 0) ? g_qc  : g_attn;
    const float* B = (MODE == 0) ? g_wic : g_woc;

    float acc[4][8][4];
    #pragma unroll
    for (int i=0;i<4;i++) for (int j=0;j<8;j++) for (int k=0;k<4;k++) acc[i][j][k]=0.f;

    auto issue = [&](int c){
        const int k0 = c*32, st = c % 3;
        const uint32_t ab = sb + (st*9216)*4;
        const uint32_t bb = sb + (27648 + st*4608)*4;
        #pragma unroll
        for (int i=0;i<8;i++){
            int fi = tid + i*256, r = fi>>3, c4 = fi&7;
            cpa16(ab + (r*36 + c4*4)*4, A + (size_t)(bm+r)*EMB + k0 + c4*4);
        }
        #pragma unroll
        for (int i=0;i<4;i++){
            int fi = tid + i*256, r = fi>>3, c4 = fi&7;
            cpa16(bb + (r*36 + c4*4)*4, B + (size_t)(bn+r)*EMB + k0 + c4*4);
        }
        CP_COMMIT();
    };

    issue(0); issue(1);
    for (int c = 0; c < KC; c++) {
        if (c + 1 < KC) { CP_WAIT(1); } else { CP_WAIT(0); }
        __syncthreads();
        const int st = c % 3;
        const float* Ab = sm + st*9216;
        const float* Bb = sm + 27648 + st*4608;
        #pragma unroll
        for (int ks = 0; ks < 4; ks++) {
            uint32_t af[4][4], bf[8][2];
            #pragma unroll
            for (int mt=0; mt<4; mt++){
                const float* p = Ab + (wm*64 + mt*16 + lr)*36 + ks*8 + lc;
                af[mt][0]=__float_as_uint(p[0]); af[mt][1]=__float_as_uint(p[8*36]);
                af[mt][2]=__float_as_uint(p[4]); af[mt][3]=__float_as_uint(p[8*36+4]);
            }
            #pragma unroll
            for (int nt=0; nt<8; nt++){
                const float* p = Bb + (wn*64 + nt*8 + lr)*36 + ks*8 + lc;
                bf[nt][0]=__float_as_uint(p[0]); bf[nt][1]=__float_as_uint(p[4]);
            }
            #pragma unroll
            for (int mt=0; mt<4; mt++)
                #pragma unroll
                for (int nt=0; nt<8; nt++)
                    mma8(acc[mt][nt], af[mt], bf[nt]);
        }
        if (c + 2 < KC) issue(c+2);
    }

    float bias0[8], bias1[8];
    #pragma unroll
    for (int nt=0; nt<8; nt++){
        int n = bn + wn*64 + nt*8 + lc*2;
        bias0[nt] = biasg[n]; bias1[nt] = biasg[n+1];
    }

    #pragma unroll
    for (int mt=0; mt<4; mt++)
    #pragma unroll
    for (int hf=0; hf<2; hf++){
        const int m = bm + wm*64 + mt*16 + hf*8 + lr;
        if (MODE == 0) {
            const int t = m >> 1, b = m & 1;
            #pragma unroll
            for (int nt=0; nt<8; nt++){
                const int n = bn + wn*64 + nt*8 + lc*2;
                float v0 = acc[mt][nt][hf*2+0] + bias0[nt];
                float v1 = acc[mt][nt][hf*2+1] + bias1[nt];
                const int which = n >> 10, e = n & 1023, h = e >> 6, d = e & 63;
                const int bh = b*NH + h;
                if (which == 0) {
                    *(float2*)&g_Q[((size_t)bh*TGT + t)*HD + d] =
                        make_float2(rt(v0*0.125f), rt(v1*0.125f));
                } else if (which == 1) {
                    *(float2*)&g_K[((size_t)bh*TGT + t)*HD + d] = make_float2(rt(v0), rt(v1));
                } else {
                    g_Vt[((size_t)bh*HD + d    )*TGT + t] = rt(v0);
                    g_Vt[((size_t)bh*HD + d + 1)*TGT + t] = rt(v1);
                }
            }
        } else {
            float* dst = Cg + (size_t)m*EMB;
            #pragma unroll
            for (int nt=0; nt<8; nt++){
                const int n = bn + wn*64 + nt*8 + lc*2;
                *(float2*)&dst[n] = make_float2(acc[mt][nt][hf*2] + bias0[nt],
                                                acc[mt][nt][hf*2+1] + bias1[nt]);
            }
        }
    }
}

// ===========================================================================
// Flash attention: 256 thr, q-tile 128 (warp=16 rows), k-chunk 64.
// 3-stage KV ring, ONE syncthreads per chunk.
// SMEM floats: Q@0(9216), stage i: K@9216+i*9216, V@+4608; P@36864(9216)
//   total 46080 floats = 184320 B
// ===========================================================================
#define FA_SMEM_BYTES (46080*4)

__global__ __launch_bounds__(256)
void flash_attn_k()
{
    constexpr int NC = TGT/64;
    extern __shared__ float sm[];
    const uint32_t sb = smem_u32(sm);
    const int tid = threadIdx.x, lane = tid & 31, w = tid >> 5;
    const int lr = lane >> 2, lc = lane & 3;
    const int qt = blockIdx.x, bh = blockIdx.y;
    const int b = bh >> 4, h = bh & 15;
    const int qbase = qt * 128;

    const float* Qg = g_Q  + (size_t)bh*TGT*HD;
    const float* Kg = g_K  + (size_t)bh*TGT*HD;
    const float* Vg = g_Vt + (size_t)bh*HD*TGT;

    float* QB = sm;
    float* PB = sm + 36864;

    auto issue_kv = [&](int kc){
        const int st = kc % 3;
        const uint32_t kb = sb + (9216 + st*9216)*4;
        const uint32_t vb = kb + 4608*4;
        #pragma unroll
        for (int i=0;i<4;i++){
            int fi = tid + i*256, r = fi>>4, c4 = fi&15;
            cpa16(kb + ((c4>=8)*2304 + r*36 + (c4&7)*4)*4,
                  Kg + (size_t)(kc*64+r)*HD + c4*4);
        }
        #pragma unroll
        for (int i=0;i<4;i++){
            int fi = tid + i*256, d = fi>>4, c4 = fi&15;
            cpa16(vb + ((c4>=8)*2304 + d*36 + (c4&7)*4)*4,
                  Vg + (size_t)d*TGT + kc*64 + c4*4);
        }
        CP_COMMIT();
    };

    // group 0: Q + KV0; group 1: KV1
    #pragma unroll
    for (int i=0;i<8;i++){
        int fi = tid + i*256, r = fi>>4, c4 = fi&15;
        cpa16(sb + ((c4>=8)*4608 + r*36 + (c4&7)*4)*4,
              Qg + (size_t)(qbase+r)*HD + c4*4);
    }
    {
        const uint32_t kb = sb + 9216*4, vb = kb + 4608*4;
        #pragma unroll
        for (int i=0;i<4;i++){
            int fi = tid + i*256, r = fi>>4, c4 = fi&15;
            cpa16(kb + ((c4>=8)*2304 + r*36 + (c4&7)*4)*4, Kg + (size_t)r*HD + c4*4);
        }
        #pragma unroll
        for (int i=0;i<4;i++){
            int fi = tid + i*256, d = fi>>4, c4 = fi&15;
            cpa16(vb + ((c4>=8)*2304 + d*36 + (c4&7)*4)*4, Vg + (size_t)d*TGT + c4*4);
        }
        CP_COMMIT();
    }
    issue_kv(1);

    float acc_o[8][4];
    #pragma unroll
    for (int j=0;j<8;j++) for (int k=0;k<4;k++) acc_o[j][k]=0.f;
    float m_r[2] = {-1e30f,-1e30f};
    float l_r[2] = {0.f,0.f};

    for (int kc = 0; kc < NC; kc++) {
        if (kc + 1 < NC) { CP_WAIT(1); } else { CP_WAIT(0); }
        __syncthreads();
        const int st = kc % 3;
        const float* KB = sm + 9216 + st*9216;
        const float* VB = KB + 4608;

        // S = Q K^T
        float s[8][4];
        #pragma unroll
        for (int j=0;j<8;j++) for (int k=0;k<4;k++) s[j][k]=0.f;
        #pragma unroll
        for (int ks=0; ks<8; ks++){
            const int hb = ks>>2, ko = (ks&3)*8;
            uint32_t af[4], bf[8][2];
            {
                const float* p = QB + hb*4608 + (w*16 + lr)*36 + ko + lc;
                af[0]=__float_as_uint(p[0]); af[1]=__float_as_uint(p[8*36]);
                af[2]=__float_as_uint(p[4]); af[3]=__float_as_uint(p[8*36+4]);
            }
            #pragma unroll
            for (int nt=0; nt<8; nt++){
                const float* p = KB + hb*2304 + (nt*8 + lr)*36 + ko + lc;
                bf[nt][0]=__float_as_uint(p[0]); bf[nt][1]=__float_as_uint(p[4]);
            }
            #pragma unroll
            for (int nt=0; nt<8; nt++)
                mma8(s[nt], af, bf[nt]);
        }

        // online softmax
        #pragma unroll
        for (int hf=0; hf<2; hf++){
            float cm = -1e30f;
            #pragma unroll
            for (int nt=0; nt<8; nt++)
                cm = fmaxf(cm, fmaxf(s[nt][hf*2], s[nt][hf*2+1]));
            cm = fmaxf(cm, __shfl_xor_sync(0xffffffffu, cm, 1));
            cm = fmaxf(cm, __shfl_xor_sync(0xffffffffu, cm, 2));
            const float mn = fmaxf(m_r[hf], cm);
            const float sc = __expf(m_r[hf] - mn);
            float cs = 0.f;
            #pragma unroll
            for (int nt=0; nt<8; nt++){
                float e0 = __expf(s[nt][hf*2]   - mn);
                float e1 = __expf(s[nt][hf*2+1] - mn);
                s[nt][hf*2] = e0; s[nt][hf*2+1] = e1;
                cs += e0 + e1;
            }
            cs += __shfl_xor_sync(0xffffffffu, cs, 1);
            cs += __shfl_xor_sync(0xffffffffu, cs, 2);
            l_r[hf] = l_r[hf]*sc + cs;
            m_r[hf] = mn;
            #pragma unroll
            for (int nt=0; nt<8; nt++){
                acc_o[nt][hf*2]   *= sc;
                acc_o[nt][hf*2+1] *= sc;
            }
        }

        // P -> smem (warp-private rows)
        #pragma unroll
        for (int nt=0; nt<8; nt++)
        #pragma unroll
        for (int hf=0; hf<2; hf++){
            const int row = w*16 + hf*8 + lr;
            float2 pv = make_float2(rt(s[nt][hf*2]), rt(s[nt][hf*2+1]));
            *(float2*)(PB + (nt>>2)*4608 + row*36 + (nt&3)*8 + lc*2) = pv;
        }
        __syncwarp();

        // O += P V
        #pragma unroll
        for (int ks=0; ks<8; ks++){
            const int hb = ks>>2, ko = (ks&3)*8;
            uint32_t af[4], bf[8][2];
            {
                const float* p = PB + hb*4608 + (w*16 + lr)*36 + ko + lc;
                af[0]=__float_as_uint(p[0]); af[1]=__float_as_uint(p[8*36]);
                af[2]=__float_as_uint(p[4]); af[3]=__float_as_uint(p[8*36+4]);
            }
            #pragma unroll
            for (int nt=0; nt<8; nt++){
                const float* p = VB + hb*2304 + (nt*8 + lr)*36 + ko + lc;
                bf[nt][0]=__float_as_uint(p[0]); bf[nt][1]=__float_as_uint(p[4]);
            }
            #pragma unroll
            for (int nt=0; nt<8; nt++)
                mma8(acc_o[nt], af, bf[nt]);
        }
        if (kc + 2 < NC) issue_kv(kc+2);
    }

    #pragma unroll
    for (int hf=0; hf<2; hf++){
        const float invl = 1.0f / l_r[hf];
        const int q = qbase + w*16 + hf*8 + lr;
        float* dst = g_attn + ((size_t)q*NBSZ + b)*EMB + h*HD;
        #pragma unroll
        for (int nt=0; nt<8; nt++)
            *(float2*)(dst + nt*8 + lc*2) =
                make_float2(rt(acc_o[nt][hf*2]*invl), rt(acc_o[nt][hf*2+1]*invl));
        if (lc == 0)
            g_stats[(size_t)bh*TGT + q] = make_float2(m_r[hf], invl);
    }
}

// ===========================================================================
// avg weights: 256 thr, block 128(q) x 64(k), warp tile 32x32.
// 3-stage QK ring over heads, ONE syncthreads per head.
// SMEM floats: stage i: Q @ i*13824 (9216), K @ i*13824+9216 (4608)
//   total 41472 floats = 165888 B
// ===========================================================================
#define AVG_SMEM_BYTES (41472*4)

__global__ __launch_bounds__(256)
void avg_attn_k(float* __restrict__ avg_out)
{
    extern __shared__ float sm[];
    const uint32_t sb = smem_u32(sm);
    const int tid = threadIdx.x, lane = tid & 31, wid = tid >> 5;
    const int wm = wid & 3, wn = wid >> 2;          // 4(q) x 2(k)
    const int lr = lane >> 2, lc = lane & 3;
    const int kt = blockIdx.x, qt = blockIdx.y, b = blockIdx.z;

    auto issue_qk = [&](int h){
        const int st = h % 3;
        const int bh = b*NH + h;
        const float* Qg = g_Q + (size_t)bh*TGT*HD;
        const float* Kg = g_K + (size_t)bh*TGT*HD;
        const uint32_t qb = sb + (st*13824)*4;
        const uint32_t kb = sb + (st*13824 + 9216)*4;
        #pragma unroll
        for (int i=0;i<8;i++){
            int fi = tid + i*256, r = fi>>4, c4 = fi&15;
            cpa16(qb + ((c4>=8)*4608 + r*36 + (c4&7)*4)*4,
                  Qg + (size_t)(qt*128+r)*HD + c4*4);
        }
        #pragma unroll
        for (int i=0;i<4;i++){
            int fi = tid + i*256, r = fi>>4, c4 = fi&15;
            cpa16(kb + ((c4>=8)*2304 + r*36 + (c4&7)*4)*4,
                  Kg + (size_t)(kt*64+r)*HD + c4*4);
        }
        CP_COMMIT();
    };

    float acc[2][4][4];
    #pragma unroll
    for (int i=0;i<2;i++) for (int j=0;j<4;j++) for (int k=0;k<4;k++) acc[i][j][k]=0.f;

    issue_qk(0); issue_qk(1);
    for (int h = 0; h < NH; h++) {
        if (h + 1 < NH) { CP_WAIT(1); } else { CP_WAIT(0); }
        __syncthreads();
        const int st = h % 3;
        const float* QB = sm + st*13824;
        const float* KB = QB + 9216;

        float s[2][4][4];
        #pragma unroll
        for (int i=0;i<2;i++) for (int j=0;j<4;j++) for (int k=0;k<4;k++) s[i][j][k]=0.f;
        #pragma unroll
        for (int ks=0; ks<8; ks++){
            const int hb = ks>>2, ko = (ks&3)*8;
            uint32_t af[2][4], bf[4][2];
            #pragma unroll
            for (int mt=0; mt<2; mt++){
                const float* p = QB + hb*4608 + (wm*32 + mt*16 + lr)*36 + ko + lc;
                af[mt][0]=__float_as_uint(p[0]); af[mt][1]=__float_as_uint(p[8*36]);
                af[mt][2]=__float_as_uint(p[4]); af[mt][3]=__float_as_uint(p[8*36+4]);
            }
            #pragma unroll
            for (int nt=0; nt<4; nt++){
                const float* p = KB + hb*2304 + (wn*32 + nt*8 + lr)*36 + ko + lc;
                bf[nt][0]=__float_as_uint(p[0]); bf[nt][1]=__float_as_uint(p[4]);
            }
            #pragma unroll
            for (int mt=0; mt<2; mt++)
                #pragma unroll
                for (int nt=0; nt<4; nt++)
                    mma8(s[mt][nt], af[mt], bf[nt]);
        }

        const int bh = b*NH + h;
        #pragma unroll
        for (int mt=0; mt<2; mt++)
        #pragma unroll
        for (int hf=0; hf<2; hf++){
            const int q = qt*128 + wm*32 + mt*16 + hf*8 + lr;
            const float2 st2 = g_stats[(size_t)bh*TGT + q];
            #pragma unroll
            for (int nt=0; nt<4; nt++){
                acc[mt][nt][hf*2]   += __expf(s[mt][nt][hf*2]   - st2.x) * st2.y;
                acc[mt][nt][hf*2+1] += __expf(s[mt][nt][hf*2+1] - st2.x) * st2.y;
            }
        }
        if (h + 2 < NH) issue_qk(h+2);
    }

    const float invH = 1.0f / NH;
    #pragma unroll
    for (int mt=0; mt<2; mt++)
    #pragma unroll
    for (int hf=0; hf<2; hf++){
        const int q = qt*128 + wm*32 + mt*16 + hf*8 + lr;
        float* dst = avg_out + ((size_t)b*TGT + q)*TGT + kt*64 + wn*32;
        #pragma unroll
        for (int nt=0; nt<4; nt++)
            *(float2*)(dst + nt*8 + lc*2) =
                make_float2(acc[mt][nt][hf*2]*invH, acc[mt][nt][hf*2+1]*invH);
    }
}

// ---------------------------------------------------------------------------
extern "C" void kernel_launch(void* const* d_in, const int* in_sizes, int n_in,
                              void* d_out, int out_size)
{
    const float* query = (const float*)d_in[0];
    const float* w_in  = (const float*)d_in[1];
    const float* b_in  = (const float*)d_in[2];
    const float* w_out = (const float*)d_in[3];
    const float* b_out = (const float*)d_in[4];

    float* out      = (float*)d_out;
    float* attn_out = out;                           // [T,B,E]
    float* avg_out  = out + (size_t)TGT*NBSZ*EMB;    // [B,T,T]

    cudaFuncSetAttribute(mma_gemm<0>,  cudaFuncAttributeMaxDynamicSharedMemorySize, GEMM_SMEM_BYTES);
    cudaFuncSetAttribute(mma_gemm<3>,  cudaFuncAttributeMaxDynamicSharedMemorySize, GEMM_SMEM_BYTES);
    cudaFuncSetAttribute(flash_attn_k, cudaFuncAttributeMaxDynamicSharedMemorySize, FA_SMEM_BYTES);
    cudaFuncSetAttribute(avg_attn_k,   cudaFuncAttributeMaxDynamicSharedMemorySize, AVG_SMEM_BYTES);

    float* d_qc;  cudaGetSymbolAddress((void**)&d_qc,  g_qc);
    float* d_wic; cudaGetSymbolAddress((void**)&d_wic, g_wic);
    float* d_woc; cudaGetSymbolAddress((void**)&d_woc, g_woc);

    // 0. pre-round inputs to tf32
    {
        int n4q = MROWS*EMB/4, n4wi = 3*EMB*EMB/4, n4wo = EMB*EMB/4;
        preround_k<<<(n4q +255)/256, 256>>>((const float4*)query, (float4*)d_qc,  n4q);
        preround_k<<<(n4wi+255)/256, 256>>>((const float4*)w_in,  (float4*)d_wic, n4wi);
        preround_k<<<(n4wo+255)/256, 256>>>((const float4*)w_out, (float4*)d_woc, n4wo);
    }

    // 1. QKV projection
    mma_gemm<0><<<dim3(3*EMB/128, MROWS/256), 256, GEMM_SMEM_BYTES>>>(nullptr, b_in);

    // 2. Flash attention
    flash_attn_k<<<dim3(TGT/128, NBH), 256, FA_SMEM_BYTES>>>();

    // 3. Averaged attention weights
    avg_attn_k<<<dim3(TGT/64, TGT/128, NBSZ), 256, AVG_SMEM_BYTES>>>(avg_out);

    // 4. Output projection
    mma_gemm<3><<<dim3(EMB/128, MROWS/256), 256, GEMM_SMEM_BYTES>>>(attn_out, b_out);
}

// round 8
// speedup vs baseline: 1.0257x; 1.0257x over previous
#include <cuda_runtime.h>
#include <cstdint>
#include <math.h>

#define TGT   2048
#define NBSZ  2
#define EMB   1024
#define NH    16
#define HD    64
#define NBH   (NBSZ*NH)      // 32
#define MROWS (TGT*NBSZ)     // 4096

// ---------------- scratch (device globals) ---------------------------------
static __device__ float  g_Q  [(size_t)NBH*TGT*HD];     // pre-rounded tf32
static __device__ float  g_K  [(size_t)NBH*TGT*HD];     // pre-rounded tf32
static __device__ float  g_Vt [(size_t)NBH*HD*TGT];     // pre-rounded tf32
static __device__ float  g_attn[(size_t)MROWS*EMB];     // pre-rounded tf32
static __device__ float2 g_stats[(size_t)NBH*TGT];      // (rowmax, 1/rowsum)
static __device__ float  g_qc [(size_t)MROWS*EMB];      // query, tf32
static __device__ float  g_wic[(size_t)3*EMB*EMB];      // in_proj_w, tf32
static __device__ float  g_woc[(size_t)EMB*EMB];        // out_w, tf32

// ---------------- helpers ---------------------------------------------------
__device__ __forceinline__ uint32_t f2tf32(float x){
    uint32_t u; asm("cvt.rna.tf32.f32 %0, %1;" : "=r"(u) : "f"(x)); return u;
}
__device__ __forceinline__ float rt(float x){ return __uint_as_float(f2tf32(x)); }
__device__ __forceinline__ float4 tf4(float4 v){
    v.x = rt(v.x); v.y = rt(v.y); v.z = rt(v.z); v.w = rt(v.w); return v;
}
__device__ __forceinline__ void mma8(float* c, const uint32_t* a, const uint32_t* b){
    asm volatile("mma.sync.aligned.m16n8k8.row.col.f32.tf32.tf32.f32 "
        "{%0,%1,%2,%3}, {%4,%5,%6,%7}, {%8,%9}, {%0,%1,%2,%3};"
        : "+f"(c[0]), "+f"(c[1]), "+f"(c[2]), "+f"(c[3])
        : "r"(a[0]), "r"(a[1]), "r"(a[2]), "r"(a[3]), "r"(b[0]), "r"(b[1]));
}
__device__ __forceinline__ uint32_t smem_u32(const void* p){
    uint32_t a; asm("{ .reg .u64 t; cvta.to.shared.u64 t, %1; cvt.u32.u64 %0, t; }":"=r"(a):"l"(p));
    return a;
}
__device__ __forceinline__ void cpa16(uint32_t s, const void* g){
    asm volatile("cp.async.cg.shared.global [%0], [%1], 16;" :: "r"(s), "l"(g) : "memory");
}
#define CP_COMMIT() asm volatile("cp.async.commit_group;" ::: "memory")
#define CP_WAIT(n)  asm volatile("cp.async.wait_group %0;" :: "n"(n) : "memory")

// ---------------- pre-round inputs to tf32 ----------------------------------
__global__ void preround_k(const float4* __restrict__ src, float4* __restrict__ dst, int n4)
{
    int i = blockIdx.x*blockDim.x + threadIdx.x;
    if (i < n4) dst[i] = tf4(src[i]);
}

// ===========================================================================
// Projection GEMMs: block 128x128, 256 thr, warp tile 64x32, 3-stage ring.
// SMEM: stage i: A @ i*9216 (128x36), B @ i*9216+4608. 27648 fl = 110592 B.
// Pattern: WAIT(1); barrier; issue(c+2); compute  (2 CTAs/SM)
// ===========================================================================
#define GEMM_SMEM_BYTES (27648*4)

template<int MODE>
__global__ __launch_bounds__(256, 2)
void mma_gemm(float* __restrict__ Cg, const float* __restrict__ biasg)
{
    constexpr int KC = 32;
    extern __shared__ float sm[];
    const uint32_t sb = smem_u32(sm);
    const int tid = threadIdx.x, lane = tid & 31, wid = tid >> 5;
    const int wm = wid & 1, wn = wid >> 1;          // 2(m) x 4(n)
    const int lr = lane >> 2, lc = lane & 3;
    const int bm = blockIdx.y * 128, bn = blockIdx.x * 128;

    const float* A = (MODE == 0) ? g_qc  : g_attn;
    const float* B = (MODE == 0) ? g_wic : g_woc;

    float acc[4][4][4];
    #pragma unroll
    for (int i=0;i<4;i++) for (int j=0;j<4;j++) for (int k=0;k<4;k++) acc[i][j][k]=0.f;

    auto issue = [&](int c){
        const int k0 = c*32, st = c % 3;
        const uint32_t ab = sb + (st*9216)*4;
        const uint32_t bb = ab + 4608*4;
        #pragma unroll
        for (int i=0;i<4;i++){
            int fi = tid + i*256, r = fi>>3, c4 = fi&7;
            cpa16(ab + (r*36 + c4*4)*4, A + (size_t)(bm+r)*EMB + k0 + c4*4);
            cpa16(bb + (r*36 + c4*4)*4, B + (size_t)(bn+r)*EMB + k0 + c4*4);
        }
        CP_COMMIT();
    };

    issue(0); issue(1);
    for (int c = 0; c < KC; c++) {
        if (c + 1 < KC) { CP_WAIT(1); } else { CP_WAIT(0); }
        __syncthreads();
        if (c + 2 < KC) issue(c+2);
        const int st = c % 3;
        const float* Ab = sm + st*9216;
        const float* Bb = Ab + 4608;
        #pragma unroll
        for (int ks = 0; ks < 4; ks++) {
            uint32_t af[4][4], bf[4][2];
            #pragma unroll
            for (int mt=0; mt<4; mt++){
                const float* p = Ab + (wm*64 + mt*16 + lr)*36 + ks*8 + lc;
                af[mt][0]=__float_as_uint(p[0]); af[mt][1]=__float_as_uint(p[8*36]);
                af[mt][2]=__float_as_uint(p[4]); af[mt][3]=__float_as_uint(p[8*36+4]);
            }
            #pragma unroll
            for (int nt=0; nt<4; nt++){
                const float* p = Bb + (wn*32 + nt*8 + lr)*36 + ks*8 + lc;
                bf[nt][0]=__float_as_uint(p[0]); bf[nt][1]=__float_as_uint(p[4]);
            }
            #pragma unroll
            for (int mt=0; mt<4; mt++)
                #pragma unroll
                for (int nt=0; nt<4; nt++)
                    mma8(acc[mt][nt], af[mt], bf[nt]);
        }
    }

    float bias0[4], bias1[4];
    #pragma unroll
    for (int nt=0; nt<4; nt++){
        int n = bn + wn*32 + nt*8 + lc*2;
        bias0[nt] = biasg[n]; bias1[nt] = biasg[n+1];
    }

    #pragma unroll
    for (int mt=0; mt<4; mt++)
    #pragma unroll
    for (int hf=0; hf<2; hf++){
        const int m = bm + wm*64 + mt*16 + hf*8 + lr;
        if (MODE == 0) {
            const int t = m >> 1, b = m & 1;
            #pragma unroll
            for (int nt=0; nt<4; nt++){
                const int n = bn + wn*32 + nt*8 + lc*2;
                float v0 = acc[mt][nt][hf*2+0] + bias0[nt];
                float v1 = acc[mt][nt][hf*2+1] + bias1[nt];
                const int which = n >> 10, e = n & 1023, h = e >> 6, d = e & 63;
                const int bh = b*NH + h;
                if (which == 0) {
                    *(float2*)&g_Q[((size_t)bh*TGT + t)*HD + d] =
                        make_float2(rt(v0*0.125f), rt(v1*0.125f));
                } else if (which == 1) {
                    *(float2*)&g_K[((size_t)bh*TGT + t)*HD + d] = make_float2(rt(v0), rt(v1));
                } else {
                    g_Vt[((size_t)bh*HD + d    )*TGT + t] = rt(v0);
                    g_Vt[((size_t)bh*HD + d + 1)*TGT + t] = rt(v1);
                }
            }
        } else {
            float* dst = Cg + (size_t)m*EMB;
            #pragma unroll
            for (int nt=0; nt<4; nt++){
                const int n = bn + wn*32 + nt*8 + lc*2;
                *(float2*)&dst[n] = make_float2(acc[mt][nt][hf*2] + bias0[nt],
                                                acc[mt][nt][hf*2+1] + bias1[nt]);
            }
        }
    }
}

// ===========================================================================
// Flash attention: 256 thr, q-tile 128 (warp=16 rows), k-chunk 32.
// 3-stage KV ring; P stays in registers (shuffle-based A-frag transpose).
// SMEM floats: Q@0 (9216); stage i @ 9216+i*4608: K (2304) + V (2304).
//   total 23040 floats = 92160 B  -> 2 CTAs/SM
// ===========================================================================
#define FA_SMEM_BYTES (23040*4)

__global__ __launch_bounds__(256, 2)
void flash_attn_k()
{
    constexpr int NC = TGT/32;
    extern __shared__ float sm[];
    const uint32_t sb = smem_u32(sm);
    const int tid = threadIdx.x, lane = tid & 31, w = tid >> 5;
    const int lr = lane >> 2, lc = lane & 3;
    const int qt = blockIdx.x, bh = blockIdx.y;
    const int b = bh >> 4, h = bh & 15;
    const int qbase = qt * 128;

    const float* Qg = g_Q  + (size_t)bh*TGT*HD;
    const float* Kg = g_K  + (size_t)bh*TGT*HD;
    const float* Vg = g_Vt + (size_t)bh*HD*TGT;

    float* QB = sm;

    auto issue_kv = [&](int kc){
        const int st = kc % 3;
        const uint32_t kb = sb + (9216 + st*4608)*4;
        const uint32_t vb = kb + 2304*4;
        #pragma unroll
        for (int i=0;i<2;i++){   // K: 32 rows x 64 cols
            int fi = tid + i*256, r = fi>>4, c4 = fi&15;
            cpa16(kb + ((c4>=8)*1152 + r*36 + (c4&7)*4)*4,
                  Kg + (size_t)(kc*32+r)*HD + c4*4);
        }
        #pragma unroll
        for (int i=0;i<2;i++){   // V: 64 d-rows x 32 t-cols
            int fi = tid + i*256, d = fi>>3, c4 = fi&7;
            cpa16(vb + (d*36 + c4*4)*4,
                  Vg + (size_t)d*TGT + kc*32 + c4*4);
        }
        CP_COMMIT();
    };

    // group 0: Q + KV0 ; group 1: KV1
    #pragma unroll
    for (int i=0;i<8;i++){
        int fi = tid + i*256, r = fi>>4, c4 = fi&15;
        cpa16(sb + ((c4>=8)*4608 + r*36 + (c4&7)*4)*4,
              Qg + (size_t)(qbase+r)*HD + c4*4);
    }
    {
        const uint32_t kb = sb + 9216*4, vb = kb + 2304*4;
        #pragma unroll
        for (int i=0;i<2;i++){
            int fi = tid + i*256, r = fi>>4, c4 = fi&15;
            cpa16(kb + ((c4>=8)*1152 + r*36 + (c4&7)*4)*4, Kg + (size_t)r*HD + c4*4);
        }
        #pragma unroll
        for (int i=0;i<2;i++){
            int fi = tid + i*256, d = fi>>3, c4 = fi&7;
            cpa16(vb + (d*36 + c4*4)*4, Vg + (size_t)d*TGT + c4*4);
        }
        CP_COMMIT();
    }
    issue_kv(1);

    float acc_o[8][4];
    #pragma unroll
    for (int j=0;j<8;j++) for (int k=0;k<4;k++) acc_o[j][k]=0.f;
    float m_r[2] = {-1e30f,-1e30f};
    float l_r[2] = {0.f,0.f};

    const unsigned FULL = 0xffffffffu;
    const int pj = lc & 1;
    const int l1 = lr*4 + (lc>>1);
    const int l2 = l1 + 2;

    for (int kc = 0; kc < NC; kc++) {
        if (kc + 1 < NC) { CP_WAIT(1); } else { CP_WAIT(0); }
        __syncthreads();
        if (kc + 2 < NC) issue_kv(kc+2);
        const int st = kc % 3;
        const float* KB = sm + 9216 + st*4608;
        const float* VB = KB + 2304;

        // S = Q K^T  (128q x 32k chunk)
        float s[4][4];
        #pragma unroll
        for (int j=0;j<4;j++) for (int k=0;k<4;k++) s[j][k]=0.f;
        #pragma unroll
        for (int ks=0; ks<8; ks++){
            const int hb = ks>>2, ko = (ks&3)*8;
            uint32_t af[4], bf[4][2];
            {
                const float* p = QB + hb*4608 + (w*16 + lr)*36 + ko + lc;
                af[0]=__float_as_uint(p[0]); af[1]=__float_as_uint(p[8*36]);
                af[2]=__float_as_uint(p[4]); af[3]=__float_as_uint(p[8*36+4]);
            }
            #pragma unroll
            for (int nt=0; nt<4; nt++){
                const float* p = KB + hb*1152 + (nt*8 + lr)*36 + ko + lc;
                bf[nt][0]=__float_as_uint(p[0]); bf[nt][1]=__float_as_uint(p[4]);
            }
            #pragma unroll
            for (int nt=0; nt<4; nt++)
                mma8(s[nt], af, bf[nt]);
        }

        // online softmax over this 32-col chunk
        #pragma unroll
        for (int hf=0; hf<2; hf++){
            float cm = -1e30f;
            #pragma unroll
            for (int nt=0; nt<4; nt++)
                cm = fmaxf(cm, fmaxf(s[nt][hf*2], s[nt][hf*2+1]));
            cm = fmaxf(cm, __shfl_xor_sync(FULL, cm, 1));
            cm = fmaxf(cm, __shfl_xor_sync(FULL, cm, 2));
            const float mn = fmaxf(m_r[hf], cm);
            const float sc = __expf(m_r[hf] - mn);
            float cs = 0.f;
            #pragma unroll
            for (int nt=0; nt<4; nt++){
                float e0 = __expf(s[nt][hf*2]   - mn);
                float e1 = __expf(s[nt][hf*2+1] - mn);
                s[nt][hf*2] = e0; s[nt][hf*2+1] = e1;
                cs += e0 + e1;
            }
            cs += __shfl_xor_sync(FULL, cs, 1);
            cs += __shfl_xor_sync(FULL, cs, 2);
            l_r[hf] = l_r[hf]*sc + cs;
            m_r[hf] = mn;
            #pragma unroll
            for (int nt=0; nt<4; nt++){
                acc_o[nt][hf*2]   *= sc;
                acc_o[nt][hf*2+1] *= sc;
                acc_o[nt+4][hf*2]   *= sc;
                acc_o[nt+4][hf*2+1] *= sc;
            }
        }

        // round P to tf32 in place
        #pragma unroll
        for (int j=0;j<4;j++) for (int k=0;k<4;k++) s[j][k] = rt(s[j][k]);

        // O += P V : A-frags from registers via shuffle, k-chunks of 8
        #pragma unroll
        for (int ks=0; ks<4; ks++){
            uint32_t af[4];
            {
                float v0 = __shfl_sync(FULL, s[ks][0], l1);
                float v1 = __shfl_sync(FULL, s[ks][1], l1);
                float v2 = __shfl_sync(FULL, s[ks][2], l1);
                float v3 = __shfl_sync(FULL, s[ks][3], l1);
                float w0 = __shfl_sync(FULL, s[ks][0], l2);
                float w1 = __shfl_sync(FULL, s[ks][1], l2);
                float w2 = __shfl_sync(FULL, s[ks][2], l2);
                float w3 = __shfl_sync(FULL, s[ks][3], l2);
                af[0] = __float_as_uint(pj ? v1 : v0);
                af[1] = __float_as_uint(pj ? v3 : v2);
                af[2] = __float_as_uint(pj ? w1 : w0);
                af[3] = __float_as_uint(pj ? w3 : w2);
            }
            #pragma unroll
            for (int nt=0; nt<8; nt++){
                uint32_t bf[2];
                const float* p = VB + (nt*8 + lr)*36 + ks*8 + lc;
                bf[0]=__float_as_uint(p[0]); bf[1]=__float_as_uint(p[4]);
                mma8(acc_o[nt], af, bf);
            }
        }
    }

    #pragma unroll
    for (int hf=0; hf<2; hf++){
        const float invl = 1.0f / l_r[hf];
        const int q = qbase + w*16 + hf*8 + lr;
        float* dst = g_attn + ((size_t)q*NBSZ + b)*EMB + h*HD;
        #pragma unroll
        for (int nt=0; nt<8; nt++)
            *(float2*)(dst + nt*8 + lc*2) =
                make_float2(rt(acc_o[nt][hf*2]*invl), rt(acc_o[nt][hf*2+1]*invl));
        if (lc == 0)
            g_stats[(size_t)bh*TGT + q] = make_float2(m_r[hf], invl);
    }
}

// ===========================================================================
// avg weights: 256 thr, block 128(q) x 64(k), warp tile 32x32, 2-stage ring.
// Pattern: WAIT(0); barrier; issue(h+1); compute.
// SMEM floats: stage i @ i*13824: Q (9216) + K (4608). 27648 fl = 110592 B.
// ===========================================================================
#define AVG_SMEM_BYTES (27648*4)

__global__ __launch_bounds__(256, 2)
void avg_attn_k(float* __restrict__ avg_out)
{
    extern __shared__ float sm[];
    const uint32_t sb = smem_u32(sm);
    const int tid = threadIdx.x, lane = tid & 31, wid = tid >> 5;
    const int wm = wid & 3, wn = wid >> 2;          // 4(q) x 2(k)
    const int lr = lane >> 2, lc = lane & 3;
    const int kt = blockIdx.x, qt = blockIdx.y, b = blockIdx.z;

    auto issue_qk = [&](int h){
        const int st = h & 1;
        const int bh = b*NH + h;
        const float* Qg = g_Q + (size_t)bh*TGT*HD;
        const float* Kg = g_K + (size_t)bh*TGT*HD;
        const uint32_t qb = sb + (st*13824)*4;
        const uint32_t kb = sb + (st*13824 + 9216)*4;
        #pragma unroll
        for (int i=0;i<8;i++){
            int fi = tid + i*256, r = fi>>4, c4 = fi&15;
            cpa16(qb + ((c4>=8)*4608 + r*36 + (c4&7)*4)*4,
                  Qg + (size_t)(qt*128+r)*HD + c4*4);
        }
        #pragma unroll
        for (int i=0;i<4;i++){
            int fi = tid + i*256, r = fi>>4, c4 = fi&15;
            cpa16(kb + ((c4>=8)*2304 + r*36 + (c4&7)*4)*4,
                  Kg + (size_t)(kt*64+r)*HD + c4*4);
        }
        CP_COMMIT();
    };

    float acc[2][4][4];
    #pragma unroll
    for (int i=0;i<2;i++) for (int j=0;j<4;j++) for (int k=0;k<4;k++) acc[i][j][k]=0.f;

    issue_qk(0);
    for (int h = 0; h < NH; h++) {
        CP_WAIT(0);
        __syncthreads();
        if (h + 1 < NH) issue_qk(h+1);
        const int st = h & 1;
        const float* QB = sm + st*13824;
        const float* KB = QB + 9216;

        float s[2][4][4];
        #pragma unroll
        for (int i=0;i<2;i++) for (int j=0;j<4;j++) for (int k=0;k<4;k++) s[i][j][k]=0.f;
        #pragma unroll
        for (int ks=0; ks<8; ks++){
            const int hb = ks>>2, ko = (ks&3)*8;
            uint32_t af[2][4], bf[4][2];
            #pragma unroll
            for (int mt=0; mt<2; mt++){
                const float* p = QB + hb*4608 + (wm*32 + mt*16 + lr)*36 + ko + lc;
                af[mt][0]=__float_as_uint(p[0]); af[mt][1]=__float_as_uint(p[8*36]);
                af[mt][2]=__float_as_uint(p[4]); af[mt][3]=__float_as_uint(p[8*36+4]);
            }
            #pragma unroll
            for (int nt=0; nt<4; nt++){
                const float* p = KB + hb*2304 + (wn*32 + nt*8 + lr)*36 + ko + lc;
                bf[nt][0]=__float_as_uint(p[0]); bf[nt][1]=__float_as_uint(p[4]);
            }
            #pragma unroll
            for (int mt=0; mt<2; mt++)
                #pragma unroll
                for (int nt=0; nt<4; nt++)
                    mma8(s[mt][nt], af[mt], bf[nt]);
        }

        const int bh = b*NH + h;
        #pragma unroll
        for (int mt=0; mt<2; mt++)
        #pragma unroll
        for (int hf=0; hf<2; hf++){
            const int q = qt*128 + wm*32 + mt*16 + hf*8 + lr;
            const float2 st2 = g_stats[(size_t)bh*TGT + q];
            #pragma unroll
            for (int nt=0; nt<4; nt++){
                acc[mt][nt][hf*2]   += __expf(s[mt][nt][hf*2]   - st2.x) * st2.y;
                acc[mt][nt][hf*2+1] += __expf(s[mt][nt][hf*2+1] - st2.x) * st2.y;
            }
        }
    }

    const float invH = 1.0f / NH;
    #pragma unroll
    for (int mt=0; mt<2; mt++)
    #pragma unroll
    for (int hf=0; hf<2; hf++){
        const int q = qt*128 + wm*32 + mt*16 + hf*8 + lr;
        float* dst = avg_out + ((size_t)b*TGT + q)*TGT + kt*64 + wn*32;
        #pragma unroll
        for (int nt=0; nt<4; nt++)
            *(float2*)(dst + nt*8 + lc*2) =
                make_float2(acc[mt][nt][hf*2]*invH, acc[mt][nt][hf*2+1]*invH);
    }
}

// ---------------------------------------------------------------------------
extern "C" void kernel_launch(void* const* d_in, const int* in_sizes, int n_in,
                              void* d_out, int out_size)
{
    const float* query = (const float*)d_in[0];
    const float* w_in  = (const float*)d_in[1];
    const float* b_in  = (const float*)d_in[2];
    const float* w_out = (const float*)d_in[3];
    const float* b_out = (const float*)d_in[4];

    float* out      = (float*)d_out;
    float* attn_out = out;                           // [T,B,E]
    float* avg_out  = out + (size_t)TGT*NBSZ*EMB;    // [B,T,T]

    cudaFuncSetAttribute(mma_gemm<0>,  cudaFuncAttributeMaxDynamicSharedMemorySize, GEMM_SMEM_BYTES);
    cudaFuncSetAttribute(mma_gemm<3>,  cudaFuncAttributeMaxDynamicSharedMemorySize, GEMM_SMEM_BYTES);
    cudaFuncSetAttribute(flash_attn_k, cudaFuncAttributeMaxDynamicSharedMemorySize, FA_SMEM_BYTES);
    cudaFuncSetAttribute(avg_attn_k,   cudaFuncAttributeMaxDynamicSharedMemorySize, AVG_SMEM_BYTES);

    float* d_qc;  cudaGetSymbolAddress((void**)&d_qc,  g_qc);
    float* d_wic; cudaGetSymbolAddress((void**)&d_wic, g_wic);
    float* d_woc; cudaGetSymbolAddress((void**)&d_woc, g_woc);

    // 0. pre-round inputs to tf32
    {
        int n4q = MROWS*EMB/4, n4wi = 3*EMB*EMB/4, n4wo = EMB*EMB/4;
        preround_k<<<(n4q +255)/256, 256>>>((const float4*)query, (float4*)d_qc,  n4q);
        preround_k<<<(n4wi+255)/256, 256>>>((const float4*)w_in,  (float4*)d_wic, n4wi);
        preround_k<<<(n4wo+255)/256, 256>>>((const float4*)w_out, (float4*)d_woc, n4wo);
    }

    // 1. QKV projection
    mma_gemm<0><<<dim3(3*EMB/128, MROWS/128), 256, GEMM_SMEM_BYTES>>>(nullptr, b_in);

    // 2. Flash attention
    flash_attn_k<<<dim3(TGT/128, NBH), 256, FA_SMEM_BYTES>>>();

    // 3. Averaged attention weights
    avg_attn_k<<<dim3(TGT/64, TGT/128, NBSZ), 256, AVG_SMEM_BYTES>>>(avg_out);

    // 4. Output projection
    mma_gemm<3><<<dim3(EMB/128, MROWS/128), 256, GEMM_SMEM_BYTES>>>(attn_out, b_out);
}

// round 9
// speedup vs baseline: 1.1243x; 1.0961x over previous
#include <cuda_runtime.h>
#include <cstdint>
#include <math.h>

#define TGT   2048
#define NBSZ  2
#define EMB   1024
#define NH    16
#define HD    64
#define NBH   (NBSZ*NH)      // 32
#define MROWS (TGT*NBSZ)     // 4096

// ---------------- scratch (device globals) ---------------------------------
static __device__ float  g_Q  [(size_t)NBH*TGT*HD];     // pre-rounded tf32
static __device__ float  g_K  [(size_t)NBH*TGT*HD];     // pre-rounded tf32
static __device__ float  g_Vt [(size_t)NBH*HD*TGT];     // pre-rounded tf32
static __device__ float  g_attn[(size_t)MROWS*EMB];     // pre-rounded tf32
static __device__ float2 g_stats[(size_t)NBH*TGT];      // (rowmax, 1/rowsum)
static __device__ float  g_qc [(size_t)MROWS*EMB];      // query, tf32
static __device__ float  g_wic[(size_t)3*EMB*EMB];      // in_proj_w, tf32
static __device__ float  g_woc[(size_t)EMB*EMB];        // out_w, tf32

// ---------------- helpers ---------------------------------------------------
__device__ __forceinline__ uint32_t f2tf32(float x){
    uint32_t u; asm("cvt.rna.tf32.f32 %0, %1;" : "=r"(u) : "f"(x)); return u;
}
__device__ __forceinline__ float rt(float x){ return __uint_as_float(f2tf32(x)); }
__device__ __forceinline__ float4 tf4(float4 v){
    v.x = rt(v.x); v.y = rt(v.y); v.z = rt(v.z); v.w = rt(v.w); return v;
}
__device__ __forceinline__ void mma8(float* c, const uint32_t* a, const uint32_t* b){
    asm volatile("mma.sync.aligned.m16n8k8.row.col.f32.tf32.tf32.f32 "
        "{%0,%1,%2,%3}, {%4,%5,%6,%7}, {%8,%9}, {%0,%1,%2,%3};"
        : "+f"(c[0]), "+f"(c[1]), "+f"(c[2]), "+f"(c[3])
        : "r"(a[0]), "r"(a[1]), "r"(a[2]), "r"(a[3]), "r"(b[0]), "r"(b[1]));
}
// tf32 fragment via ldmatrix: an 8x4 tf32 tile == an 8x8 b16 matrix.
__device__ __forceinline__ void ldsm4(uint32_t& r0, uint32_t& r1, uint32_t& r2,
                                      uint32_t& r3, uint32_t addr){
    asm volatile("ldmatrix.sync.aligned.m8n8.x4.shared.b16 {%0,%1,%2,%3}, [%4];"
        : "=r"(r0), "=r"(r1), "=r"(r2), "=r"(r3) : "r"(addr));
}
__device__ __forceinline__ uint32_t smem_u32(const void* p){
    uint32_t a; asm("{ .reg .u64 t; cvta.to.shared.u64 t, %1; cvt.u32.u64 %0, t; }":"=r"(a):"l"(p));
    return a;
}
__device__ __forceinline__ void cpa16(uint32_t s, const void* g){
    asm volatile("cp.async.cg.shared.global [%0], [%1], 16;" :: "r"(s), "l"(g) : "memory");
}
#define CP_COMMIT() asm volatile("cp.async.commit_group;" ::: "memory")
#define CP_WAIT(n)  asm volatile("cp.async.wait_group %0;" :: "n"(n) : "memory")

// ldmatrix per-lane offsets (floats) within a tile of stride-36 rows.
// A-pattern: matrices (rows0-7,k0-3),(rows8-15,k0-3),(rows0-7,k4-7),(rows8-15,k4-7)
//   -> regs r0..r3 == af[0..3]
#define LDSM_A_OFF(j, rowbase) \
    ((((rowbase) + (((j)>>3)&1)*8 + ((j)&7))*36) + (((j)>>4)*4))
// B-pattern (pair of n-tiles): matrices (nt0,k0-3),(nt0,k4-7),(nt1,k0-3),(nt1,k4-7)
//   -> regs r0..r3 == bf[nt0][0],bf[nt0][1],bf[nt1][0],bf[nt1][1]
#define LDSM_B_OFF(j, rowbase) \
    ((((rowbase) + (((j)>>4)*8) + ((j)&7))*36) + ((((j)>>3)&1)*4))

// ---------------- pre-round inputs to tf32 ----------------------------------
__global__ void preround_k(const float4* __restrict__ src, float4* __restrict__ dst, int n4)
{
    int i = blockIdx.x*blockDim.x + threadIdx.x;
    if (i < n4) dst[i] = tf4(src[i]);
}

// ===========================================================================
// Projection GEMMs: block 128x128, 256 thr, warp tile 64x32, 3-stage ring.
// SMEM: stage i: A @ i*9216 (128x36), B @ i*9216+4608. 27648 fl = 110592 B.
// ===========================================================================
#define GEMM_SMEM_BYTES (27648*4)

template<int MODE>
__global__ __launch_bounds__(256, 2)
void mma_gemm(float* __restrict__ Cg, const float* __restrict__ biasg)
{
    constexpr int KC = 32;
    extern __shared__ float sm[];
    const uint32_t sb = smem_u32(sm);
    const int tid = threadIdx.x, lane = tid & 31, wid = tid >> 5;
    const int wm = wid & 1, wn = wid >> 1;          // 2(m) x 4(n)
    const int lr = lane >> 2, lc = lane & 3;
    const int bm = blockIdx.y * 128, bn = blockIdx.x * 128;

    const float* A = (MODE == 0) ? g_qc  : g_attn;
    const float* B = (MODE == 0) ? g_wic : g_woc;

    const uint32_t aoff = LDSM_A_OFF(lane, wm*64) * 4;
    const uint32_t boff = LDSM_B_OFF(lane, wn*32) * 4;

    float acc[4][4][4];
    #pragma unroll
    for (int i=0;i<4;i++) for (int j=0;j<4;j++) for (int k=0;k<4;k++) acc[i][j][k]=0.f;

    auto issue = [&](int c){
        const int k0 = c*32, st = c % 3;
        const uint32_t ab = sb + (st*9216)*4;
        const uint32_t bb = ab + 4608*4;
        #pragma unroll
        for (int i=0;i<4;i++){
            int fi = tid + i*256, r = fi>>3, c4 = fi&7;
            cpa16(ab + (r*36 + c4*4)*4, A + (size_t)(bm+r)*EMB + k0 + c4*4);
            cpa16(bb + (r*36 + c4*4)*4, B + (size_t)(bn+r)*EMB + k0 + c4*4);
        }
        CP_COMMIT();
    };

    issue(0); issue(1);
    for (int c = 0; c < KC; c++) {
        if (c + 1 < KC) { CP_WAIT(1); } else { CP_WAIT(0); }
        __syncthreads();
        if (c + 2 < KC) issue(c+2);
        const int st = c % 3;
        const uint32_t Ab = sb + (st*9216)*4;
        const uint32_t Bb = Ab + 4608*4;
        #pragma unroll
        for (int ks = 0; ks < 4; ks++) {
            uint32_t af[4][4], bf[4][2];
            #pragma unroll
            for (int mt=0; mt<4; mt++)
                ldsm4(af[mt][0], af[mt][1], af[mt][2], af[mt][3],
                      Ab + aoff + (mt*576 + ks*8)*4);
            #pragma unroll
            for (int p=0; p<2; p++)
                ldsm4(bf[2*p][0], bf[2*p][1], bf[2*p+1][0], bf[2*p+1][1],
                      Bb + boff + (p*576 + ks*8)*4);
            #pragma unroll
            for (int mt=0; mt<4; mt++)
                #pragma unroll
                for (int nt=0; nt<4; nt++)
                    mma8(acc[mt][nt], af[mt], bf[nt]);
        }
    }

    float bias0[4], bias1[4];
    #pragma unroll
    for (int nt=0; nt<4; nt++){
        int n = bn + wn*32 + nt*8 + lc*2;
        bias0[nt] = biasg[n]; bias1[nt] = biasg[n+1];
    }

    #pragma unroll
    for (int mt=0; mt<4; mt++)
    #pragma unroll
    for (int hf=0; hf<2; hf++){
        const int m = bm + wm*64 + mt*16 + hf*8 + lr;
        if (MODE == 0) {
            const int t = m >> 1, b = m & 1;
            #pragma unroll
            for (int nt=0; nt<4; nt++){
                const int n = bn + wn*32 + nt*8 + lc*2;
                float v0 = acc[mt][nt][hf*2+0] + bias0[nt];
                float v1 = acc[mt][nt][hf*2+1] + bias1[nt];
                const int which = n >> 10, e = n & 1023, h = e >> 6, d = e & 63;
                const int bh = b*NH + h;
                if (which == 0) {
                    *(float2*)&g_Q[((size_t)bh*TGT + t)*HD + d] =
                        make_float2(rt(v0*0.125f), rt(v1*0.125f));
                } else if (which == 1) {
                    *(float2*)&g_K[((size_t)bh*TGT + t)*HD + d] = make_float2(rt(v0), rt(v1));
                } else {
                    g_Vt[((size_t)bh*HD + d    )*TGT + t] = rt(v0);
                    g_Vt[((size_t)bh*HD + d + 1)*TGT + t] = rt(v1);
                }
            }
        } else {
            float* dst = Cg + (size_t)m*EMB;
            #pragma unroll
            for (int nt=0; nt<4; nt++){
                const int n = bn + wn*32 + nt*8 + lc*2;
                *(float2*)&dst[n] = make_float2(acc[mt][nt][hf*2] + bias0[nt],
                                                acc[mt][nt][hf*2+1] + bias1[nt]);
            }
        }
    }
}

// ===========================================================================
// Flash attention: 256 thr, q-tile 128 (warp=16 rows), k-chunk 32.
// 3-stage KV ring; P in registers (shuffle A-frag transpose); ldmatrix loads.
// SMEM floats: Q@0 (9216); stage i @ 9216+i*4608: K (2304) + V (2304).
//   total 23040 floats = 92160 B
// ===========================================================================
#define FA_SMEM_BYTES (23040*4)

__global__ __launch_bounds__(256, 2)
void flash_attn_k()
{
    constexpr int NC = TGT/32;
    extern __shared__ float sm[];
    const uint32_t sb = smem_u32(sm);
    const int tid = threadIdx.x, lane = tid & 31, w = tid >> 5;
    const int lr = lane >> 2, lc = lane & 3;
    const int qt = blockIdx.x, bh = blockIdx.y;
    const int b = bh >> 4, h = bh & 15;
    const int qbase = qt * 128;

    const float* Qg = g_Q  + (size_t)bh*TGT*HD;
    const float* Kg = g_K  + (size_t)bh*TGT*HD;
    const float* Vg = g_Vt + (size_t)bh*HD*TGT;

    const uint32_t qoff = LDSM_A_OFF(lane, w*16) * 4;
    const uint32_t koff = LDSM_B_OFF(lane, 0) * 4;
    const uint32_t voff = LDSM_B_OFF(lane, 0) * 4;

    auto issue_kv = [&](int kc){
        const int st = kc % 3;
        const uint32_t kb = sb + (9216 + st*4608)*4;
        const uint32_t vb = kb + 2304*4;
        #pragma unroll
        for (int i=0;i<2;i++){   // K: 32 rows x 64 cols
            int fi = tid + i*256, r = fi>>4, c4 = fi&15;
            cpa16(kb + ((c4>=8)*1152 + r*36 + (c4&7)*4)*4,
                  Kg + (size_t)(kc*32+r)*HD + c4*4);
        }
        #pragma unroll
        for (int i=0;i<2;i++){   // V: 64 d-rows x 32 t-cols
            int fi = tid + i*256, d = fi>>3, c4 = fi&7;
            cpa16(vb + (d*36 + c4*4)*4,
                  Vg + (size_t)d*TGT + kc*32 + c4*4);
        }
        CP_COMMIT();
    };

    // group 0: Q + KV0 ; group 1: KV1
    #pragma unroll
    for (int i=0;i<8;i++){
        int fi = tid + i*256, r = fi>>4, c4 = fi&15;
        cpa16(sb + ((c4>=8)*4608 + r*36 + (c4&7)*4)*4,
              Qg + (size_t)(qbase+r)*HD + c4*4);
    }
    {
        const uint32_t kb = sb + 9216*4, vb = kb + 2304*4;
        #pragma unroll
        for (int i=0;i<2;i++){
            int fi = tid + i*256, r = fi>>4, c4 = fi&15;
            cpa16(kb + ((c4>=8)*1152 + r*36 + (c4&7)*4)*4, Kg + (size_t)r*HD + c4*4);
        }
        #pragma unroll
        for (int i=0;i<2;i++){
            int fi = tid + i*256, d = fi>>3, c4 = fi&7;
            cpa16(vb + (d*36 + c4*4)*4, Vg + (size_t)d*TGT + c4*4);
        }
        CP_COMMIT();
    }
    issue_kv(1);

    float acc_o[8][4];
    #pragma unroll
    for (int j=0;j<8;j++) for (int k=0;k<4;k++) acc_o[j][k]=0.f;
    float m_r[2] = {-1e30f,-1e30f};
    float l_r[2] = {0.f,0.f};

    const unsigned FULL = 0xffffffffu;
    const int pj = lc & 1;
    const int l1 = lr*4 + (lc>>1);
    const int l2 = l1 + 2;

    for (int kc = 0; kc < NC; kc++) {
        if (kc + 1 < NC) { CP_WAIT(1); } else { CP_WAIT(0); }
        __syncthreads();
        if (kc + 2 < NC) issue_kv(kc+2);
        const int st = kc % 3;
        const uint32_t KBu = sb + (9216 + st*4608)*4;
        const uint32_t VBu = KBu + 2304*4;

        // S = Q K^T  (128q x 32k chunk)
        float s[4][4];
        #pragma unroll
        for (int j=0;j<4;j++) for (int k=0;k<4;k++) s[j][k]=0.f;
        #pragma unroll
        for (int ks=0; ks<8; ks++){
            const int hb = ks>>2, ko = (ks&3)*8;
            uint32_t af[4], bf[4][2];
            ldsm4(af[0], af[1], af[2], af[3], sb + (hb*4608)*4 + qoff + ko*4);
            #pragma unroll
            for (int p=0; p<2; p++)
                ldsm4(bf[2*p][0], bf[2*p][1], bf[2*p+1][0], bf[2*p+1][1],
                      KBu + (hb*1152)*4 + koff + (p*576 + ko)*4);
            #pragma unroll
            for (int nt=0; nt<4; nt++)
                mma8(s[nt], af, bf[nt]);
        }

        // online softmax over this 32-col chunk
        #pragma unroll
        for (int hf=0; hf<2; hf++){
            float cm = -1e30f;
            #pragma unroll
            for (int nt=0; nt<4; nt++)
                cm = fmaxf(cm, fmaxf(s[nt][hf*2], s[nt][hf*2+1]));
            cm = fmaxf(cm, __shfl_xor_sync(FULL, cm, 1));
            cm = fmaxf(cm, __shfl_xor_sync(FULL, cm, 2));
            const float mn = fmaxf(m_r[hf], cm);
            const float sc = __expf(m_r[hf] - mn);
            float cs = 0.f;
            #pragma unroll
            for (int nt=0; nt<4; nt++){
                float e0 = __expf(s[nt][hf*2]   - mn);
                float e1 = __expf(s[nt][hf*2+1] - mn);
                s[nt][hf*2] = e0; s[nt][hf*2+1] = e1;
                cs += e0 + e1;
            }
            cs += __shfl_xor_sync(FULL, cs, 1);
            cs += __shfl_xor_sync(FULL, cs, 2);
            l_r[hf] = l_r[hf]*sc + cs;
            m_r[hf] = mn;
            #pragma unroll
            for (int nt=0; nt<4; nt++){
                acc_o[nt][hf*2]     *= sc;
                acc_o[nt][hf*2+1]   *= sc;
                acc_o[nt+4][hf*2]   *= sc;
                acc_o[nt+4][hf*2+1] *= sc;
            }
        }

        // round P to tf32 in place
        #pragma unroll
        for (int j=0;j<4;j++) for (int k=0;k<4;k++) s[j][k] = rt(s[j][k]);

        // O += P V : A-frags from registers via shuffle, k-chunks of 8
        #pragma unroll
        for (int ks=0; ks<4; ks++){
            uint32_t af[4];
            {
                float v0 = __shfl_sync(FULL, s[ks][0], l1);
                float v1 = __shfl_sync(FULL, s[ks][1], l1);
                float v2 = __shfl_sync(FULL, s[ks][2], l1);
                float v3 = __shfl_sync(FULL, s[ks][3], l1);
                float w0 = __shfl_sync(FULL, s[ks][0], l2);
                float w1 = __shfl_sync(FULL, s[ks][1], l2);
                float w2 = __shfl_sync(FULL, s[ks][2], l2);
                float w3 = __shfl_sync(FULL, s[ks][3], l2);
                af[0] = __float_as_uint(pj ? v1 : v0);
                af[1] = __float_as_uint(pj ? v3 : v2);
                af[2] = __float_as_uint(pj ? w1 : w0);
                af[3] = __float_as_uint(pj ? w3 : w2);
            }
            uint32_t vf[8][2];
            #pragma unroll
            for (int p=0; p<4; p++)
                ldsm4(vf[2*p][0], vf[2*p][1], vf[2*p+1][0], vf[2*p+1][1],
                      VBu + voff + (p*576 + ks*8)*4);
            #pragma unroll
            for (int nt=0; nt<8; nt++)
                mma8(acc_o[nt], af, vf[nt]);
        }
    }

    #pragma unroll
    for (int hf=0; hf<2; hf++){
        const float invl = 1.0f / l_r[hf];
        const int q = qbase + w*16 + hf*8 + lr;
        float* dst = g_attn + ((size_t)q*NBSZ + b)*EMB + h*HD;
        #pragma unroll
        for (int nt=0; nt<8; nt++)
            *(float2*)(dst + nt*8 + lc*2) =
                make_float2(rt(acc_o[nt][hf*2]*invl), rt(acc_o[nt][hf*2+1]*invl));
        if (lc == 0)
            g_stats[(size_t)bh*TGT + q] = make_float2(m_r[hf], invl);
    }
}

// ===========================================================================
// avg weights: 256 thr, block 128(q) x 64(k), warp tile 32x32, 2-stage ring.
// SMEM floats: stage i @ i*13824: Q (9216) + K (4608). 27648 fl = 110592 B.
// ===========================================================================
#define AVG_SMEM_BYTES (27648*4)

__global__ __launch_bounds__(256, 2)
void avg_attn_k(float* __restrict__ avg_out)
{
    extern __shared__ float sm[];
    const uint32_t sb = smem_u32(sm);
    const int tid = threadIdx.x, lane = tid & 31, wid = tid >> 5;
    const int wm = wid & 3, wn = wid >> 2;          // 4(q) x 2(k)
    const int lr = lane >> 2, lc = lane & 3;
    const int kt = blockIdx.x, qt = blockIdx.y, b = blockIdx.z;

    const uint32_t aoff = LDSM_A_OFF(lane, wm*32) * 4;
    const uint32_t boff = LDSM_B_OFF(lane, wn*32) * 4;

    auto issue_qk = [&](int h){
        const int st = h & 1;
        const int bh = b*NH + h;
        const float* Qg = g_Q + (size_t)bh*TGT*HD;
        const float* Kg = g_K + (size_t)bh*TGT*HD;
        const uint32_t qb = sb + (st*13824)*4;
        const uint32_t kb = sb + (st*13824 + 9216)*4;
        #pragma unroll
        for (int i=0;i<8;i++){
            int fi = tid + i*256, r = fi>>4, c4 = fi&15;
            cpa16(qb + ((c4>=8)*4608 + r*36 + (c4&7)*4)*4,
                  Qg + (size_t)(qt*128+r)*HD + c4*4);
        }
        #pragma unroll
        for (int i=0;i<4;i++){
            int fi = tid + i*256, r = fi>>4, c4 = fi&15;
            cpa16(kb + ((c4>=8)*2304 + r*36 + (c4&7)*4)*4,
                  Kg + (size_t)(kt*64+r)*HD + c4*4);
        }
        CP_COMMIT();
    };

    float acc[2][4][4];
    #pragma unroll
    for (int i=0;i<2;i++) for (int j=0;j<4;j++) for (int k=0;k<4;k++) acc[i][j][k]=0.f;

    issue_qk(0);
    for (int h = 0; h < NH; h++) {
        CP_WAIT(0);
        __syncthreads();
        if (h + 1 < NH) issue_qk(h+1);
        const int st = h & 1;
        const uint32_t QBu = sb + (st*13824)*4;
        const uint32_t KBu = sb + (st*13824 + 9216)*4;

        float s[2][4][4];
        #pragma unroll
        for (int i=0;i<2;i++) for (int j=0;j<4;j++) for (int k=0;k<4;k++) s[i][j][k]=0.f;
        #pragma unroll
        for (int ks=0; ks<8; ks++){
            const int hb = ks>>2, ko = (ks&3)*8;
            uint32_t af[2][4], bf[4][2];
            #pragma unroll
            for (int mt=0; mt<2; mt++)
                ldsm4(af[mt][0], af[mt][1], af[mt][2], af[mt][3],
                      QBu + (hb*4608)*4 + aoff + (mt*576 + ko)*4);
            #pragma unroll
            for (int p=0; p<2; p++)
                ldsm4(bf[2*p][0], bf[2*p][1], bf[2*p+1][0], bf[2*p+1][1],
                      KBu + (hb*2304)*4 + boff + (p*576 + ko)*4);
            #pragma unroll
            for (int mt=0; mt<2; mt++)
                #pragma unroll
                for (int nt=0; nt<4; nt++)
                    mma8(s[mt][nt], af[mt], bf[nt]);
        }

        const int bh = b*NH + h;
        #pragma unroll
        for (int mt=0; mt<2; mt++)
        #pragma unroll
        for (int hf=0; hf<2; hf++){
            const int q = qt*128 + wm*32 + mt*16 + hf*8 + lr;
            const float2 st2 = g_stats[(size_t)bh*TGT + q];
            #pragma unroll
            for (int nt=0; nt<4; nt++){
                acc[mt][nt][hf*2]   += __expf(s[mt][nt][hf*2]   - st2.x) * st2.y;
                acc[mt][nt][hf*2+1] += __expf(s[mt][nt][hf*2+1] - st2.x) * st2.y;
            }
        }
    }

    const float invH = 1.0f / NH;
    #pragma unroll
    for (int mt=0; mt<2; mt++)
    #pragma unroll
    for (int hf=0; hf<2; hf++){
        const int q = qt*128 + wm*32 + mt*16 + hf*8 + lr;
        float* dst = avg_out + ((size_t)b*TGT + q)*TGT + kt*64 + wn*32;
        #pragma unroll
        for (int nt=0; nt<4; nt++)
            *(float2*)(dst + nt*8 + lc*2) =
                make_float2(acc[mt][nt][hf*2]*invH, acc[mt][nt][hf*2+1]*invH);
    }
}

// ---------------------------------------------------------------------------
extern "C" void kernel_launch(void* const* d_in, const int* in_sizes, int n_in,
                              void* d_out, int out_size)
{
    const float* query = (const float*)d_in[0];
    const float* w_in  = (const float*)d_in[1];
    const float* b_in  = (const float*)d_in[2];
    const float* w_out = (const float*)d_in[3];
    const float* b_out = (const float*)d_in[4];

    float* out      = (float*)d_out;
    float* attn_out = out;                           // [T,B,E]
    float* avg_out  = out + (size_t)TGT*NBSZ*EMB;    // [B,T,T]

    cudaFuncSetAttribute(mma_gemm<0>,  cudaFuncAttributeMaxDynamicSharedMemorySize, GEMM_SMEM_BYTES);
    cudaFuncSetAttribute(mma_gemm<3>,  cudaFuncAttributeMaxDynamicSharedMemorySize, GEMM_SMEM_BYTES);
    cudaFuncSetAttribute(flash_attn_k, cudaFuncAttributeMaxDynamicSharedMemorySize, FA_SMEM_BYTES);
    cudaFuncSetAttribute(avg_attn_k,   cudaFuncAttributeMaxDynamicSharedMemorySize, AVG_SMEM_BYTES);

    float* d_qc;  cudaGetSymbolAddress((void**)&d_qc,  g_qc);
    float* d_wic; cudaGetSymbolAddress((void**)&d_wic, g_wic);
    float* d_woc; cudaGetSymbolAddress((void**)&d_woc, g_woc);

    // 0. pre-round inputs to tf32
    {
        int n4q = MROWS*EMB/4, n4wi = 3*EMB*EMB/4, n4wo = EMB*EMB/4;
        preround_k<<<(n4q +255)/256, 256>>>((const float4*)query, (float4*)d_qc,  n4q);
        preround_k<<<(n4wi+255)/256, 256>>>((const float4*)w_in,  (float4*)d_wic, n4wi);
        preround_k<<<(n4wo+255)/256, 256>>>((const float4*)w_out, (float4*)d_woc, n4wo);
    }

    // 1. QKV projection
    mma_gemm<0><<<dim3(3*EMB/128, MROWS/128), 256, GEMM_SMEM_BYTES>>>(nullptr, b_in);

    // 2. Flash attention
    flash_attn_k<<<dim3(TGT/128, NBH), 256, FA_SMEM_BYTES>>>();

    // 3. Averaged attention weights
    avg_attn_k<<<dim3(TGT/64, TGT/128, NBSZ), 256, AVG_SMEM_BYTES>>>(avg_out);

    // 4. Output projection
    mma_gemm<3><<<dim3(EMB/128, MROWS/128), 256, GEMM_SMEM_BYTES>>>(attn_out, b_out);
}

// round 11
// speedup vs baseline: 1.1393x; 1.0133x over previous
#include <cuda_runtime.h>
#include <cstdint>
#include <math.h>

#define TGT   2048
#define NBSZ  2
#define EMB   1024
#define NH    16
#define HD    64
#define NBH   (NBSZ*NH)      // 32
#define MROWS (TGT*NBSZ)     // 4096

// ---------------- scratch (device globals) ---------------------------------
static __device__ float  g_Q  [(size_t)NBH*TGT*HD];     // pre-rounded tf32
static __device__ float  g_K  [(size_t)NBH*TGT*HD];     // pre-rounded tf32
static __device__ float  g_Vt [(size_t)NBH*HD*TGT];     // pre-rounded tf32
static __device__ float  g_attn[(size_t)MROWS*EMB];     // pre-rounded tf32
static __device__ float2 g_stats[(size_t)NBH*TGT];      // (rowmax, 1/rowsum)
static __device__ float  g_qc [(size_t)MROWS*EMB];      // query, tf32
static __device__ float  g_wic[(size_t)3*EMB*EMB];      // in_proj_w, tf32
static __device__ float  g_woc[(size_t)EMB*EMB];        // out_w, tf32

// ---------------- helpers ---------------------------------------------------
__device__ __forceinline__ uint32_t f2tf32(float x){
    uint32_t u; asm("cvt.rna.tf32.f32 %0, %1;" : "=r"(u) : "f"(x)); return u;
}
__device__ __forceinline__ float rt(float x){ return __uint_as_float(f2tf32(x)); }
__device__ __forceinline__ float4 tf4(float4 v){
    v.x = rt(v.x); v.y = rt(v.y); v.z = rt(v.z); v.w = rt(v.w); return v;
}
__device__ __forceinline__ void mma8(float* c, const uint32_t* a, const uint32_t* b){
    asm volatile("mma.sync.aligned.m16n8k8.row.col.f32.tf32.tf32.f32 "
        "{%0,%1,%2,%3}, {%4,%5,%6,%7}, {%8,%9}, {%0,%1,%2,%3};"
        : "+f"(c[0]), "+f"(c[1]), "+f"(c[2]), "+f"(c[3])
        : "r"(a[0]), "r"(a[1]), "r"(a[2]), "r"(a[3]), "r"(b[0]), "r"(b[1]));
}
// tf32 fragment via ldmatrix: an 8x4 tf32 tile == an 8x8 b16 matrix.
__device__ __forceinline__ void ldsm4(uint32_t& r0, uint32_t& r1, uint32_t& r2,
                                      uint32_t& r3, uint32_t addr){
    asm volatile("ldmatrix.sync.aligned.m8n8.x4.shared.b16 {%0,%1,%2,%3}, [%4];"
        : "=r"(r0), "=r"(r1), "=r"(r2), "=r"(r3) : "r"(addr));
}
__device__ __forceinline__ uint32_t smem_u32(const void* p){
    uint32_t a; asm("{ .reg .u64 t; cvta.to.shared.u64 t, %1; cvt.u32.u64 %0, t; }":"=r"(a):"l"(p));
    return a;
}
__device__ __forceinline__ void cpa16(uint32_t s, const void* g){
    asm volatile("cp.async.cg.shared.global [%0], [%1], 16;" :: "r"(s), "l"(g) : "memory");
}
#define CP_COMMIT() asm volatile("cp.async.commit_group;" ::: "memory")
#define CP_WAIT(n)  asm volatile("cp.async.wait_group %0;" :: "n"(n) : "memory")

// ldmatrix per-lane offsets (floats) within a tile of stride-36 rows.
#define LDSM_A_OFF(j, rowbase) \
    ((((rowbase) + (((j)>>3)&1)*8 + ((j)&7))*36) + (((j)>>4)*4))
#define LDSM_B_OFF(j, rowbase) \
    ((((rowbase) + (((j)>>4)*8) + ((j)&7))*36) + ((((j)>>3)&1)*4))

#define L2E 1.4426950408889634f

// ---------------- fused pre-round (one launch) ------------------------------
__global__ void preround_all_k(const float4* __restrict__ q,
                               const float4* __restrict__ wi,
                               const float4* __restrict__ wo,
                               float4* __restrict__ dq,
                               float4* __restrict__ dwi,
                               float4* __restrict__ dwo)
{
    const int NQ = MROWS*EMB/4, NWI = 3*EMB*EMB/4, NWO = EMB*EMB/4;
    int i = blockIdx.x*blockDim.x + threadIdx.x;
    if (i < NQ)                 dq [i]          = tf4(q [i]);
    else if (i < NQ+NWI)        dwi[i-NQ]       = tf4(wi[i-NQ]);
    else if (i < NQ+NWI+NWO)    dwo[i-NQ-NWI]   = tf4(wo[i-NQ-NWI]);
}

// ===========================================================================
// Projection GEMMs: block 128x128, 256 thr, warp tile 64x32, 3-stage ring.
// (unchanged — validated round 9)
// ===========================================================================
#define GEMM_SMEM_BYTES (27648*4)

template<int MODE>
__global__ __launch_bounds__(256, 2)
void mma_gemm(float* __restrict__ Cg, const float* __restrict__ biasg)
{
    constexpr int KC = 32;
    extern __shared__ float sm[];
    const uint32_t sb = smem_u32(sm);
    const int tid = threadIdx.x, lane = tid & 31, wid = tid >> 5;
    const int wm = wid & 1, wn = wid >> 1;
    const int lr = lane >> 2, lc = lane & 3;
    const int bm = blockIdx.y * 128, bn = blockIdx.x * 128;

    const float* A = (MODE == 0) ? g_qc  : g_attn;
    const float* B = (MODE == 0) ? g_wic : g_woc;

    const uint32_t aoff = LDSM_A_OFF(lane, wm*64) * 4;
    const uint32_t boff = LDSM_B_OFF(lane, wn*32) * 4;

    float acc[4][4][4];
    #pragma unroll
    for (int i=0;i<4;i++) for (int j=0;j<4;j++) for (int k=0;k<4;k++) acc[i][j][k]=0.f;

    auto issue = [&](int c){
        const int k0 = c*32, st = c % 3;
        const uint32_t ab = sb + (st*9216)*4;
        const uint32_t bb = ab + 4608*4;
        #pragma unroll
        for (int i=0;i<4;i++){
            int fi = tid + i*256, r = fi>>3, c4 = fi&7;
            cpa16(ab + (r*36 + c4*4)*4, A + (size_t)(bm+r)*EMB + k0 + c4*4);
            cpa16(bb + (r*36 + c4*4)*4, B + (size_t)(bn+r)*EMB + k0 + c4*4);
        }
        CP_COMMIT();
    };

    issue(0); issue(1);
    for (int c = 0; c < KC; c++) {
        if (c + 1 < KC) { CP_WAIT(1); } else { CP_WAIT(0); }
        __syncthreads();
        if (c + 2 < KC) issue(c+2);
        const int st = c % 3;
        const uint32_t Ab = sb + (st*9216)*4;
        const uint32_t Bb = Ab + 4608*4;
        #pragma unroll
        for (int ks = 0; ks < 4; ks++) {
            uint32_t af[4][4], bf[4][2];
            #pragma unroll
            for (int mt=0; mt<4; mt++)
                ldsm4(af[mt][0], af[mt][1], af[mt][2], af[mt][3],
                      Ab + aoff + (mt*576 + ks*8)*4);
            #pragma unroll
            for (int p=0; p<2; p++)
                ldsm4(bf[2*p][0], bf[2*p][1], bf[2*p+1][0], bf[2*p+1][1],
                      Bb + boff + (p*576 + ks*8)*4);
            #pragma unroll
            for (int mt=0; mt<4; mt++)
                #pragma unroll
                for (int nt=0; nt<4; nt++)
                    mma8(acc[mt][nt], af[mt], bf[nt]);
        }
    }

    float bias0[4], bias1[4];
    #pragma unroll
    for (int nt=0; nt<4; nt++){
        int n = bn + wn*32 + nt*8 + lc*2;
        bias0[nt] = biasg[n]; bias1[nt] = biasg[n+1];
    }

    #pragma unroll
    for (int mt=0; mt<4; mt++)
    #pragma unroll
    for (int hf=0; hf<2; hf++){
        const int m = bm + wm*64 + mt*16 + hf*8 + lr;
        if (MODE == 0) {
            const int t = m >> 1, b = m & 1;
            #pragma unroll
            for (int nt=0; nt<4; nt++){
                const int n = bn + wn*32 + nt*8 + lc*2;
                float v0 = acc[mt][nt][hf*2+0] + bias0[nt];
                float v1 = acc[mt][nt][hf*2+1] + bias1[nt];
                const int which = n >> 10, e = n & 1023, h = e >> 6, d = e & 63;
                const int bh = b*NH + h;
                if (which == 0) {
                    *(float2*)&g_Q[((size_t)bh*TGT + t)*HD + d] =
                        make_float2(rt(v0*0.125f), rt(v1*0.125f));
                } else if (which == 1) {
                    *(float2*)&g_K[((size_t)bh*TGT + t)*HD + d] = make_float2(rt(v0), rt(v1));
                } else {
                    g_Vt[((size_t)bh*HD + d    )*TGT + t] = rt(v0);
                    g_Vt[((size_t)bh*HD + d + 1)*TGT + t] = rt(v1);
                }
            }
        } else {
            float* dst = Cg + (size_t)m*EMB;
            #pragma unroll
            for (int nt=0; nt<4; nt++){
                const int n = bn + wn*32 + nt*8 + lc*2;
                *(float2*)&dst[n] = make_float2(acc[mt][nt][hf*2] + bias0[nt],
                                                acc[mt][nt][hf*2+1] + bias1[nt]);
            }
        }
    }
}

// ===========================================================================
// Flash attention: 256 thr, q-tile 128 (warp=16 rows), k-chunk 32.
// 4-stage KV ring, ONE chunk per barrier, prefetch distance 3.
// Safety: issue(kc+3) writes stage (kc+3)&3 == (kc-1)&3, whose readers all
// finished in round kc-1 and are fenced by this round's __syncthreads.
// SMEM floats: Q@0 (9216); stage i @ 9216+i*4608: K (2304) + V (2304).
//   total 27648 floats = 110592 B -> 2 CTAs/SM
// ===========================================================================
#define FA_SMEM_BYTES (27648*4)

__global__ __launch_bounds__(256, 2)
void flash_attn_k()
{
    constexpr int NC = TGT/32;          // 64 chunks
    extern __shared__ float sm[];
    const uint32_t sb = smem_u32(sm);
    const int tid = threadIdx.x, lane = tid & 31, w = tid >> 5;
    const int lr = lane >> 2, lc = lane & 3;
    const int qt = blockIdx.x, bh = blockIdx.y;
    const int b = bh >> 4, h = bh & 15;
    const int qbase = qt * 128;

    const float* Qg = g_Q  + (size_t)bh*TGT*HD;
    const float* Kg = g_K  + (size_t)bh*TGT*HD;
    const float* Vg = g_Vt + (size_t)bh*HD*TGT;

    const uint32_t qoff = LDSM_A_OFF(lane, w*16) * 4;
    const uint32_t koff = LDSM_B_OFF(lane, 0) * 4;

    auto issue_kv = [&](int kc){
        const int st = kc & 3;
        const uint32_t kb = sb + (9216 + st*4608)*4;
        const uint32_t vb = kb + 2304*4;
        #pragma unroll
        for (int i=0;i<2;i++){   // K: 32 rows x 64 cols
            int fi = tid + i*256, r = fi>>4, c4 = fi&15;
            cpa16(kb + ((c4>=8)*1152 + r*36 + (c4&7)*4)*4,
                  Kg + (size_t)(kc*32+r)*HD + c4*4);
        }
        #pragma unroll
        for (int i=0;i<2;i++){   // V: 64 d-rows x 32 t-cols
            int fi = tid + i*256, d = fi>>3, c4 = fi&7;
            cpa16(vb + (d*36 + c4*4)*4,
                  Vg + (size_t)d*TGT + kc*32 + c4*4);
        }
        CP_COMMIT();
    };

    // prologue: group0 = Q + KV0, then KV1, KV2  (prefetch depth 3)
    #pragma unroll
    for (int i=0;i<8;i++){
        int fi = tid + i*256, r = fi>>4, c4 = fi&15;
        cpa16(sb + ((c4>=8)*4608 + r*36 + (c4&7)*4)*4,
              Qg + (size_t)(qbase+r)*HD + c4*4);
    }
    {
        const uint32_t kb = sb + 9216*4, vb = kb + 2304*4;
        #pragma unroll
        for (int i=0;i<2;i++){
            int fi = tid + i*256, r = fi>>4, c4 = fi&15;
            cpa16(kb + ((c4>=8)*1152 + r*36 + (c4&7)*4)*4, Kg + (size_t)r*HD + c4*4);
        }
        #pragma unroll
        for (int i=0;i<2;i++){
            int fi = tid + i*256, d = fi>>3, c4 = fi&7;
            cpa16(vb + (d*36 + c4*4)*4, Vg + (size_t)d*TGT + c4*4);
        }
        CP_COMMIT();
    }
    issue_kv(1); issue_kv(2);

    float acc_o[8][4];
    #pragma unroll
    for (int j=0;j<8;j++) for (int k=0;k<4;k++) acc_o[j][k]=0.f;
    float m_r[2] = {-1e30f,-1e30f};
    float l_r[2] = {0.f,0.f};

    const unsigned FULL = 0xffffffffu;
    const int pj = lc & 1;
    const int l1 = lr*4 + (lc>>1);
    const int l2 = l1 + 2;

    for (int kc = 0; kc < NC; kc++) {
        if (kc + 2 < NC)      { CP_WAIT(2); }
        else if (kc + 1 < NC) { CP_WAIT(1); }
        else                  { CP_WAIT(0); }
        __syncthreads();
        if (kc + 3 < NC) issue_kv(kc + 3);

        const int st = kc & 3;
        const uint32_t KBu = sb + (9216 + st*4608)*4;
        const uint32_t VBu = KBu + 2304*4;

        // S = Q K^T  (128q x 32k chunk)
        float s[4][4];
        #pragma unroll
        for (int j=0;j<4;j++) for (int k=0;k<4;k++) s[j][k]=0.f;
        #pragma unroll
        for (int ks=0; ks<8; ks++){
            const int hb = ks>>2, ko = (ks&3)*8;
            uint32_t af[4], bf[4][2];
            ldsm4(af[0], af[1], af[2], af[3], sb + (hb*4608)*4 + qoff + ko*4);
            #pragma unroll
            for (int p=0; p<2; p++)
                ldsm4(bf[2*p][0], bf[2*p][1], bf[2*p+1][0], bf[2*p+1][1],
                      KBu + (hb*1152)*4 + koff + (p*576 + ko)*4);
            #pragma unroll
            for (int nt=0; nt<4; nt++)
                mma8(s[nt], af, bf[nt]);
        }

        // online softmax over this 32-col chunk
        #pragma unroll
        for (int hf=0; hf<2; hf++){
            float cm = -1e30f;
            #pragma unroll
            for (int nt=0; nt<4; nt++)
                cm = fmaxf(cm, fmaxf(s[nt][hf*2], s[nt][hf*2+1]));
            cm = fmaxf(cm, __shfl_xor_sync(FULL, cm, 1));
            cm = fmaxf(cm, __shfl_xor_sync(FULL, cm, 2));
            const float mn = fmaxf(m_r[hf], cm);
            const float sc = __expf(m_r[hf] - mn);
            float cs = 0.f;
            #pragma unroll
            for (int nt=0; nt<4; nt++){
                float e0 = __expf(s[nt][hf*2]   - mn);
                float e1 = __expf(s[nt][hf*2+1] - mn);
                s[nt][hf*2] = e0; s[nt][hf*2+1] = e1;
                cs += e0 + e1;
            }
            cs += __shfl_xor_sync(FULL, cs, 1);
            cs += __shfl_xor_sync(FULL, cs, 2);
            l_r[hf] = l_r[hf]*sc + cs;
            m_r[hf] = mn;
            #pragma unroll
            for (int nt=0; nt<4; nt++){
                acc_o[nt][hf*2]     *= sc;
                acc_o[nt][hf*2+1]   *= sc;
                acc_o[nt+4][hf*2]   *= sc;
                acc_o[nt+4][hf*2+1] *= sc;
            }
        }

        // round P to tf32 in place
        #pragma unroll
        for (int j=0;j<4;j++) for (int k=0;k<4;k++) s[j][k] = rt(s[j][k]);

        // O += P V : A-frags from registers via shuffle
        #pragma unroll
        for (int ks=0; ks<4; ks++){
            uint32_t af[4];
            {
                float v0 = __shfl_sync(FULL, s[ks][0], l1);
                float v1 = __shfl_sync(FULL, s[ks][1], l1);
                float v2 = __shfl_sync(FULL, s[ks][2], l1);
                float v3 = __shfl_sync(FULL, s[ks][3], l1);
                float w0 = __shfl_sync(FULL, s[ks][0], l2);
                float w1 = __shfl_sync(FULL, s[ks][1], l2);
                float w2 = __shfl_sync(FULL, s[ks][2], l2);
                float w3 = __shfl_sync(FULL, s[ks][3], l2);
                af[0] = __float_as_uint(pj ? v1 : v0);
                af[1] = __float_as_uint(pj ? v3 : v2);
                af[2] = __float_as_uint(pj ? w1 : w0);
                af[3] = __float_as_uint(pj ? w3 : w2);
            }
            uint32_t vf[8][2];
            #pragma unroll
            for (int p=0; p<4; p++)
                ldsm4(vf[2*p][0], vf[2*p][1], vf[2*p+1][0], vf[2*p+1][1],
                      VBu + koff + (p*576 + ks*8)*4);
            #pragma unroll
            for (int nt=0; nt<8; nt++)
                mma8(acc_o[nt], af, vf[nt]);
        }
    }

    #pragma unroll
    for (int hf=0; hf<2; hf++){
        const float invl = 1.0f / l_r[hf];
        const int q = qbase + w*16 + hf*8 + lr;
        float* dst = g_attn + ((size_t)q*NBSZ + b)*EMB + h*HD;
        #pragma unroll
        for (int nt=0; nt<8; nt++)
            *(float2*)(dst + nt*8 + lc*2) =
                make_float2(rt(acc_o[nt][hf*2]*invl), rt(acc_o[nt][hf*2+1]*invl));
        if (lc == 0)
            g_stats[(size_t)bh*TGT + q] = make_float2(m_r[hf], invl);
    }
}

// ===========================================================================
// avg weights: 256 thr, block 128(q) x 64(k), warp tile 32x32, 2-stage ring.
// exp folded to single exp2: p = exp2(S*log2e + c), c = log2(invl) - m*log2e.
// ===========================================================================
#define AVG_SMEM_BYTES (27648*4)

__global__ __launch_bounds__(256, 2)
void avg_attn_k(float* __restrict__ avg_out)
{
    extern __shared__ float sm[];
    const uint32_t sb = smem_u32(sm);
    const int tid = threadIdx.x, lane = tid & 31, wid = tid >> 5;
    const int wm = wid & 3, wn = wid >> 2;          // 4(q) x 2(k)
    const int lr = lane >> 2, lc = lane & 3;
    const int kt = blockIdx.x, qt = blockIdx.y, b = blockIdx.z;

    const uint32_t aoff = LDSM_A_OFF(lane, wm*32) * 4;
    const uint32_t boff = LDSM_B_OFF(lane, wn*32) * 4;

    auto issue_qk = [&](int h){
        const int st = h & 1;
        const int bh = b*NH + h;
        const float* Qg = g_Q + (size_t)bh*TGT*HD;
        const float* Kg = g_K + (size_t)bh*TGT*HD;
        const uint32_t qb = sb + (st*13824)*4;
        const uint32_t kb = sb + (st*13824 + 9216)*4;
        #pragma unroll
        for (int i=0;i<8;i++){
            int fi = tid + i*256, r = fi>>4, c4 = fi&15;
            cpa16(qb + ((c4>=8)*4608 + r*36 + (c4&7)*4)*4,
                  Qg + (size_t)(qt*128+r)*HD + c4*4);
        }
        #pragma unroll
        for (int i=0;i<4;i++){
            int fi = tid + i*256, r = fi>>4, c4 = fi&15;
            cpa16(kb + ((c4>=8)*2304 + r*36 + (c4&7)*4)*4,
                  Kg + (size_t)(kt*64+r)*HD + c4*4);
        }
        CP_COMMIT();
    };

    float acc[2][4][4];
    #pragma unroll
    for (int i=0;i<2;i++) for (int j=0;j<4;j++) for (int k=0;k<4;k++) acc[i][j][k]=0.f;

    issue_qk(0);
    for (int h = 0; h < NH; h++) {
        CP_WAIT(0);
        __syncthreads();
        if (h + 1 < NH) issue_qk(h+1);
        const int st = h & 1;
        const uint32_t QBu = sb + (st*13824)*4;
        const uint32_t KBu = sb + (st*13824 + 9216)*4;

        // prefetch stats for this head (q rows owned by this thread)
        const int bh = b*NH + h;
        float crow[2][2];
        #pragma unroll
        for (int mt=0; mt<2; mt++)
        #pragma unroll
        for (int hf=0; hf<2; hf++){
            const int q = qt*128 + wm*32 + mt*16 + hf*8 + lr;
            const float2 st2 = g_stats[(size_t)bh*TGT + q];
            crow[mt][hf] = __log2f(st2.y) - st2.x * L2E;
        }

        float s[2][4][4];
        #pragma unroll
        for (int i=0;i<2;i++) for (int j=0;j<4;j++) for (int k=0;k<4;k++) s[i][j][k]=0.f;
        #pragma unroll
        for (int ks=0; ks<8; ks++){
            const int hb = ks>>2, ko = (ks&3)*8;
            uint32_t af[2][4], bf[4][2];
            #pragma unroll
            for (int mt=0; mt<2; mt++)
                ldsm4(af[mt][0], af[mt][1], af[mt][2], af[mt][3],
                      QBu + (hb*4608)*4 + aoff + (mt*576 + ko)*4);
            #pragma unroll
            for (int p=0; p<2; p++)
                ldsm4(bf[2*p][0], bf[2*p][1], bf[2*p+1][0], bf[2*p+1][1],
                      KBu + (hb*2304)*4 + boff + (p*576 + ko)*4);
            #pragma unroll
            for (int mt=0; mt<2; mt++)
                #pragma unroll
                for (int nt=0; nt<4; nt++)
                    mma8(s[mt][nt], af[mt], bf[nt]);
        }

        #pragma unroll
        for (int mt=0; mt<2; mt++)
        #pragma unroll
        for (int hf=0; hf<2; hf++){
            const float c = crow[mt][hf];
            #pragma unroll
            for (int nt=0; nt<4; nt++){
                acc[mt][nt][hf*2]   += exp2f(fmaf(s[mt][nt][hf*2],   L2E, c));
                acc[mt][nt][hf*2+1] += exp2f(fmaf(s[mt][nt][hf*2+1], L2E, c));
            }
        }
    }

    const float invH = 1.0f / NH;
    #pragma unroll
    for (int mt=0; mt<2; mt++)
    #pragma unroll
    for (int hf=0; hf<2; hf++){
        const int q = qt*128 + wm*32 + mt*16 + hf*8 + lr;
        float* dst = avg_out + ((size_t)b*TGT + q)*TGT + kt*64 + wn*32;
        #pragma unroll
        for (int nt=0; nt<4; nt++)
            *(float2*)(dst + nt*8 + lc*2) =
                make_float2(acc[mt][nt][hf*2]*invH, acc[mt][nt][hf*2+1]*invH);
    }
}

// ---------------------------------------------------------------------------
extern "C" void kernel_launch(void* const* d_in, const int* in_sizes, int n_in,
                              void* d_out, int out_size)
{
    const float* query = (const float*)d_in[0];
    const float* w_in  = (const float*)d_in[1];
    const float* b_in  = (const float*)d_in[2];
    const float* w_out = (const float*)d_in[3];
    const float* b_out = (const float*)d_in[4];

    float* out      = (float*)d_out;
    float* attn_out = out;                           // [T,B,E]
    float* avg_out  = out + (size_t)TGT*NBSZ*EMB;    // [B,T,T]

    cudaFuncSetAttribute(mma_gemm<0>,  cudaFuncAttributeMaxDynamicSharedMemorySize, GEMM_SMEM_BYTES);
    cudaFuncSetAttribute(mma_gemm<3>,  cudaFuncAttributeMaxDynamicSharedMemorySize, GEMM_SMEM_BYTES);
    cudaFuncSetAttribute(flash_attn_k, cudaFuncAttributeMaxDynamicSharedMemorySize, FA_SMEM_BYTES);
    cudaFuncSetAttribute(avg_attn_k,   cudaFuncAttributeMaxDynamicSharedMemorySize, AVG_SMEM_BYTES);

    float* d_qc;  cudaGetSymbolAddress((void**)&d_qc,  g_qc);
    float* d_wic; cudaGetSymbolAddress((void**)&d_wic, g_wic);
    float* d_woc; cudaGetSymbolAddress((void**)&d_woc, g_woc);

    // 0. pre-round inputs to tf32 (single launch)
    {
        int total = MROWS*EMB/4 + 3*EMB*EMB/4 + EMB*EMB/4;
        preround_all_k<<<(total+255)/256, 256>>>(
            (const float4*)query, (const float4*)w_in, (const float4*)w_out,
            (float4*)d_qc, (float4*)d_wic, (float4*)d_woc);
    }

    // 1. QKV projection
    mma_gemm<0><<<dim3(3*EMB/128, MROWS/128), 256, GEMM_SMEM_BYTES>>>(nullptr, b_in);

    // 2. Flash attention
    flash_attn_k<<<dim3(TGT/128, NBH), 256, FA_SMEM_BYTES>>>();

    // 3. Averaged attention weights
    avg_attn_k<<<dim3(TGT/64, TGT/128, NBSZ), 256, AVG_SMEM_BYTES>>>(avg_out);

    // 4. Output projection
    mma_gemm<3><<<dim3(EMB/128, MROWS/128), 256, GEMM_SMEM_BYTES>>>(attn_out, b_out);
}

// round 12
// speedup vs baseline: 1.2858x; 1.1286x over previous
#include <cuda_runtime.h>
#include <cuda_fp16.h>
#include <cstdint>
#include <math.h>

#define TGT   2048
#define NBSZ  2
#define EMB   1024
#define NH    16
#define HD    64
#define NBH   (NBSZ*NH)      // 32
#define MROWS (TGT*NBSZ)     // 4096

// ---------------- scratch (device globals) ---------------------------------
static __device__ float  g_Q  [(size_t)NBH*TGT*HD];     // pre-rounded tf32
static __device__ float  g_K  [(size_t)NBH*TGT*HD];     // pre-rounded tf32
static __device__ __half g_Vt [(size_t)NBH*HD*TGT];     // fp16 (== tf32 mantissa)
static __device__ float  g_attn[(size_t)MROWS*EMB];     // pre-rounded tf32
static __device__ float2 g_stats[(size_t)NBH*TGT];      // (rowmax, 1/rowsum)
static __device__ float  g_qc [(size_t)MROWS*EMB];      // query, tf32
static __device__ float  g_wic[(size_t)3*EMB*EMB];      // in_proj_w, tf32
static __device__ float  g_woc[(size_t)EMB*EMB];        // out_w, tf32

// ---------------- helpers ---------------------------------------------------
__device__ __forceinline__ uint32_t f2tf32(float x){
    uint32_t u; asm("cvt.rna.tf32.f32 %0, %1;" : "=r"(u) : "f"(x)); return u;
}
__device__ __forceinline__ float rt(float x){ return __uint_as_float(f2tf32(x)); }
__device__ __forceinline__ float4 tf4(float4 v){
    v.x = rt(v.x); v.y = rt(v.y); v.z = rt(v.z); v.w = rt(v.w); return v;
}
__device__ __forceinline__ void mma8(float* c, const uint32_t* a, const uint32_t* b){
    asm volatile("mma.sync.aligned.m16n8k8.row.col.f32.tf32.tf32.f32 "
        "{%0,%1,%2,%3}, {%4,%5,%6,%7}, {%8,%9}, {%0,%1,%2,%3};"
        : "+f"(c[0]), "+f"(c[1]), "+f"(c[2]), "+f"(c[3])
        : "r"(a[0]), "r"(a[1]), "r"(a[2]), "r"(a[3]), "r"(b[0]), "r"(b[1]));
}
// fp16 MMA for P*V (fp16 mantissa == tf32 mantissa; P in [0,1], V ~ N(0,1))
__device__ __forceinline__ void mma16h(float* c, const uint32_t* a, const uint32_t* b){
    asm volatile("mma.sync.aligned.m16n8k16.row.col.f32.f16.f16.f32 "
        "{%0,%1,%2,%3}, {%4,%5,%6,%7}, {%8,%9}, {%0,%1,%2,%3};"
        : "+f"(c[0]), "+f"(c[1]), "+f"(c[2]), "+f"(c[3])
        : "r"(a[0]), "r"(a[1]), "r"(a[2]), "r"(a[3]), "r"(b[0]), "r"(b[1]));
}
// pack {hi, lo} floats -> f16x2 reg
__device__ __forceinline__ uint32_t pack_h2(float hi, float lo){
    uint32_t r; asm("cvt.rn.f16x2.f32 %0, %1, %2;" : "=r"(r) : "f"(hi), "f"(lo));
    return r;
}
// tf32 fragment via ldmatrix: an 8x4 tf32 tile == an 8x8 b16 matrix.
__device__ __forceinline__ void ldsm4(uint32_t& r0, uint32_t& r1, uint32_t& r2,
                                      uint32_t& r3, uint32_t addr){
    asm volatile("ldmatrix.sync.aligned.m8n8.x4.shared.b16 {%0,%1,%2,%3}, [%4];"
        : "=r"(r0), "=r"(r1), "=r"(r2), "=r"(r3) : "r"(addr));
}
__device__ __forceinline__ uint32_t smem_u32(const void* p){
    uint32_t a; asm("{ .reg .u64 t; cvta.to.shared.u64 t, %1; cvt.u32.u64 %0, t; }":"=r"(a):"l"(p));
    return a;
}
__device__ __forceinline__ void cpa16(uint32_t s, const void* g){
    asm volatile("cp.async.cg.shared.global [%0], [%1], 16;" :: "r"(s), "l"(g) : "memory");
}
#define CP_COMMIT() asm volatile("cp.async.commit_group;" ::: "memory")
#define CP_WAIT(n)  asm volatile("cp.async.wait_group %0;" :: "n"(n) : "memory")

// ldmatrix per-lane offsets (floats) within a tile of stride-36 rows.
#define LDSM_A_OFF(j, rowbase) \
    ((((rowbase) + (((j)>>3)&1)*8 + ((j)&7))*36) + (((j)>>4)*4))
#define LDSM_B_OFF(j, rowbase) \
    ((((rowbase) + (((j)>>4)*8) + ((j)&7))*36) + ((((j)>>3)&1)*4))

#define L2E 1.4426950408889634f

// ---------------- fused pre-round (one launch) ------------------------------
__global__ void preround_all_k(const float4* __restrict__ q,
                               const float4* __restrict__ wi,
                               const float4* __restrict__ wo,
                               float4* __restrict__ dq,
                               float4* __restrict__ dwi,
                               float4* __restrict__ dwo)
{
    const int NQ = MROWS*EMB/4, NWI = 3*EMB*EMB/4, NWO = EMB*EMB/4;
    int i = blockIdx.x*blockDim.x + threadIdx.x;
    if (i < NQ)                 dq [i]          = tf4(q [i]);
    else if (i < NQ+NWI)        dwi[i-NQ]       = tf4(wi[i-NQ]);
    else if (i < NQ+NWI+NWO)    dwo[i-NQ-NWI]   = tf4(wo[i-NQ-NWI]);
}

// ===========================================================================
// Projection GEMMs: block 128x128, 256 thr, warp tile 64x32, 3-stage ring.
// (validated round 9; only V epilogue changed to fp16 store)
// ===========================================================================
#define GEMM_SMEM_BYTES (27648*4)

template<int MODE>
__global__ __launch_bounds__(256, 2)
void mma_gemm(float* __restrict__ Cg, const float* __restrict__ biasg)
{
    constexpr int KC = 32;
    extern __shared__ float sm[];
    const uint32_t sb = smem_u32(sm);
    const int tid = threadIdx.x, lane = tid & 31, wid = tid >> 5;
    const int wm = wid & 1, wn = wid >> 1;
    const int lr = lane >> 2, lc = lane & 3;
    const int bm = blockIdx.y * 128, bn = blockIdx.x * 128;

    const float* A = (MODE == 0) ? g_qc  : g_attn;
    const float* B = (MODE == 0) ? g_wic : g_woc;

    const uint32_t aoff = LDSM_A_OFF(lane, wm*64) * 4;
    const uint32_t boff = LDSM_B_OFF(lane, wn*32) * 4;

    float acc[4][4][4];
    #pragma unroll
    for (int i=0;i<4;i++) for (int j=0;j<4;j++) for (int k=0;k<4;k++) acc[i][j][k]=0.f;

    auto issue = [&](int c){
        const int k0 = c*32, st = c % 3;
        const uint32_t ab = sb + (st*9216)*4;
        const uint32_t bb = ab + 4608*4;
        #pragma unroll
        for (int i=0;i<4;i++){
            int fi = tid + i*256, r = fi>>3, c4 = fi&7;
            cpa16(ab + (r*36 + c4*4)*4, A + (size_t)(bm+r)*EMB + k0 + c4*4);
            cpa16(bb + (r*36 + c4*4)*4, B + (size_t)(bn+r)*EMB + k0 + c4*4);
        }
        CP_COMMIT();
    };

    issue(0); issue(1);
    for (int c = 0; c < KC; c++) {
        if (c + 1 < KC) { CP_WAIT(1); } else { CP_WAIT(0); }
        __syncthreads();
        if (c + 2 < KC) issue(c+2);
        const int st = c % 3;
        const uint32_t Ab = sb + (st*9216)*4;
        const uint32_t Bb = Ab + 4608*4;
        #pragma unroll
        for (int ks = 0; ks < 4; ks++) {
            uint32_t af[4][4], bf[4][2];
            #pragma unroll
            for (int mt=0; mt<4; mt++)
                ldsm4(af[mt][0], af[mt][1], af[mt][2], af[mt][3],
                      Ab + aoff + (mt*576 + ks*8)*4);
            #pragma unroll
            for (int p=0; p<2; p++)
                ldsm4(bf[2*p][0], bf[2*p][1], bf[2*p+1][0], bf[2*p+1][1],
                      Bb + boff + (p*576 + ks*8)*4);
            #pragma unroll
            for (int mt=0; mt<4; mt++)
                #pragma unroll
                for (int nt=0; nt<4; nt++)
                    mma8(acc[mt][nt], af[mt], bf[nt]);
        }
    }

    float bias0[4], bias1[4];
    #pragma unroll
    for (int nt=0; nt<4; nt++){
        int n = bn + wn*32 + nt*8 + lc*2;
        bias0[nt] = biasg[n]; bias1[nt] = biasg[n+1];
    }

    #pragma unroll
    for (int mt=0; mt<4; mt++)
    #pragma unroll
    for (int hf=0; hf<2; hf++){
        const int m = bm + wm*64 + mt*16 + hf*8 + lr;
        if (MODE == 0) {
            const int t = m >> 1, b = m & 1;
            #pragma unroll
            for (int nt=0; nt<4; nt++){
                const int n = bn + wn*32 + nt*8 + lc*2;
                float v0 = acc[mt][nt][hf*2+0] + bias0[nt];
                float v1 = acc[mt][nt][hf*2+1] + bias1[nt];
                const int which = n >> 10, e = n & 1023, h = e >> 6, d = e & 63;
                const int bh = b*NH + h;
                if (which == 0) {
                    *(float2*)&g_Q[((size_t)bh*TGT + t)*HD + d] =
                        make_float2(rt(v0*0.125f), rt(v1*0.125f));
                } else if (which == 1) {
                    *(float2*)&g_K[((size_t)bh*TGT + t)*HD + d] = make_float2(rt(v0), rt(v1));
                } else {
                    g_Vt[((size_t)bh*HD + d    )*TGT + t] = __float2half(v0);
                    g_Vt[((size_t)bh*HD + d + 1)*TGT + t] = __float2half(v1);
                }
            }
        } else {
            float* dst = Cg + (size_t)m*EMB;
            #pragma unroll
            for (int nt=0; nt<4; nt++){
                const int n = bn + wn*32 + nt*8 + lc*2;
                *(float2*)&dst[n] = make_float2(acc[mt][nt][hf*2] + bias0[nt],
                                                acc[mt][nt][hf*2+1] + bias1[nt]);
            }
        }
    }
}

// ===========================================================================
// Flash attention: 256 thr, q-tile 128 (warp=16 rows), k-chunk 32.
// 4-stage KV ring, prefetch distance 3. PV in fp16 (zero-shuffle A-frags).
// SMEM floats: Q@0 (9216); stage i @ 9216+i*3584: K (2304 fl) + V fp16
//   (64 rows x stride 40 halfs = 2560 halfs = 1280 fl).
//   total = 9216 + 4*3584 = 23552 fl = 94208 B -> 2 CTAs/SM
// ===========================================================================
#define FA_STAGE_FL 3584
#define FA_SMEM_BYTES ((9216 + 4*FA_STAGE_FL)*4)

__global__ __launch_bounds__(256, 2)
void flash_attn_k()
{
    constexpr int NC = TGT/32;          // 64 chunks
    extern __shared__ float sm[];
    const uint32_t sb = smem_u32(sm);
    const int tid = threadIdx.x, lane = tid & 31, w = tid >> 5;
    const int lr = lane >> 2, lc = lane & 3;
    const int qt = blockIdx.x, bh = blockIdx.y;
    const int b = bh >> 4, h = bh & 15;
    const int qbase = qt * 128;

    const float*  Qg = g_Q  + (size_t)bh*TGT*HD;
    const float*  Kg = g_K  + (size_t)bh*TGT*HD;
    const __half* Vg = g_Vt + (size_t)bh*HD*TGT;

    const uint32_t qoff = LDSM_A_OFF(lane, w*16) * 4;
    const uint32_t koff = LDSM_B_OFF(lane, 0) * 4;
    // V fp16 ldsm lane offset (halfs): row = (lane>>4)*8 + (lane&7), kblk = (lane>>3)&1
    const uint32_t voff = (((lane & 7) + ((lane >> 4) << 3)) * 40 + ((lane >> 3) & 1) * 8);

    auto issue_kv = [&](int kc){
        const int st = kc & 3;
        const uint32_t kb = sb + (9216 + st*FA_STAGE_FL)*4;
        const uint32_t vb = kb + 2304*4;
        #pragma unroll
        for (int i=0;i<2;i++){   // K: 32 rows x 64 cols fp32
            int fi = tid + i*256, r = fi>>4, c4 = fi&15;
            cpa16(kb + ((c4>=8)*1152 + r*36 + (c4&7)*4)*4,
                  Kg + (size_t)(kc*32+r)*HD + c4*4);
        }
        {                        // V: 64 d-rows x 32 t-cols fp16 (1 cpa/thread)
            int d = tid >> 2, c4 = tid & 3;
            cpa16(vb + (d*40 + c4*8)*2,
                  Vg + (size_t)d*TGT + kc*32 + c4*8);
        }
        CP_COMMIT();
    };

    // prologue: group0 = Q + KV0, then KV1, KV2  (prefetch depth 3)
    #pragma unroll
    for (int i=0;i<8;i++){
        int fi = tid + i*256, r = fi>>4, c4 = fi&15;
        cpa16(sb + ((c4>=8)*4608 + r*36 + (c4&7)*4)*4,
              Qg + (size_t)(qbase+r)*HD + c4*4);
    }
    {
        const uint32_t kb = sb + 9216*4, vb = kb + 2304*4;
        #pragma unroll
        for (int i=0;i<2;i++){
            int fi = tid + i*256, r = fi>>4, c4 = fi&15;
            cpa16(kb + ((c4>=8)*1152 + r*36 + (c4&7)*4)*4, Kg + (size_t)r*HD + c4*4);
        }
        {
            int d = tid >> 2, c4 = tid & 3;
            cpa16(vb + (d*40 + c4*8)*2, Vg + (size_t)d*TGT + c4*8);
        }
        CP_COMMIT();
    }
    issue_kv(1); issue_kv(2);

    float acc_o[8][4];
    #pragma unroll
    for (int j=0;j<8;j++) for (int k=0;k<4;k++) acc_o[j][k]=0.f;
    float m_r[2] = {-1e30f,-1e30f};
    float l_r[2] = {0.f,0.f};

    const unsigned FULL = 0xffffffffu;

    for (int kc = 0; kc < NC; kc++) {
        if (kc + 2 < NC)      { CP_WAIT(2); }
        else if (kc + 1 < NC) { CP_WAIT(1); }
        else                  { CP_WAIT(0); }
        __syncthreads();
        if (kc + 3 < NC) issue_kv(kc + 3);

        const int st = kc & 3;
        const uint32_t KBu = sb + (9216 + st*FA_STAGE_FL)*4;
        const uint32_t VBu = KBu + 2304*4;

        // S = Q K^T  (128q x 32k chunk, tf32)
        float s[4][4];
        #pragma unroll
        for (int j=0;j<4;j++) for (int k=0;k<4;k++) s[j][k]=0.f;
        #pragma unroll
        for (int ks=0; ks<8; ks++){
            const int hb = ks>>2, ko = (ks&3)*8;
            uint32_t af[4], bf[4][2];
            ldsm4(af[0], af[1], af[2], af[3], sb + (hb*4608)*4 + qoff + ko*4);
            #pragma unroll
            for (int p=0; p<2; p++)
                ldsm4(bf[2*p][0], bf[2*p][1], bf[2*p+1][0], bf[2*p+1][1],
                      KBu + (hb*1152)*4 + koff + (p*576 + ko)*4);
            #pragma unroll
            for (int nt=0; nt<4; nt++)
                mma8(s[nt], af, bf[nt]);
        }

        // online softmax over this 32-col chunk
        #pragma unroll
        for (int hf=0; hf<2; hf++){
            float cm = -1e30f;
            #pragma unroll
            for (int nt=0; nt<4; nt++)
                cm = fmaxf(cm, fmaxf(s[nt][hf*2], s[nt][hf*2+1]));
            cm = fmaxf(cm, __shfl_xor_sync(FULL, cm, 1));
            cm = fmaxf(cm, __shfl_xor_sync(FULL, cm, 2));
            const float mn = fmaxf(m_r[hf], cm);
            const float sc = __expf(m_r[hf] - mn);
            float cs = 0.f;
            #pragma unroll
            for (int nt=0; nt<4; nt++){
                float e0 = __expf(s[nt][hf*2]   - mn);
                float e1 = __expf(s[nt][hf*2+1] - mn);
                s[nt][hf*2] = e0; s[nt][hf*2+1] = e1;
                cs += e0 + e1;
            }
            cs += __shfl_xor_sync(FULL, cs, 1);
            cs += __shfl_xor_sync(FULL, cs, 2);
            l_r[hf] = l_r[hf]*sc + cs;
            m_r[hf] = mn;
            #pragma unroll
            for (int nt=0; nt<4; nt++){
                acc_o[nt][hf*2]     *= sc;
                acc_o[nt][hf*2+1]   *= sc;
                acc_o[nt+4][hf*2]   *= sc;
                acc_o[nt+4][hf*2+1] *= sc;
            }
        }

        // O += P V  in fp16: A-frags packed straight from S C-frags (no shuffles)
        #pragma unroll
        for (int ks2=0; ks2<2; ks2++){
            uint32_t a[4];
            a[0] = pack_h2(s[2*ks2  ][1], s[2*ks2  ][0]);   // row lr,   k 2lc,2lc+1
            a[1] = pack_h2(s[2*ks2  ][3], s[2*ks2  ][2]);   // row lr+8
            a[2] = pack_h2(s[2*ks2+1][1], s[2*ks2+1][0]);   // k+8
            a[3] = pack_h2(s[2*ks2+1][3], s[2*ks2+1][2]);
            #pragma unroll
            for (int p=0; p<4; p++){
                uint32_t b0, b1, b2, b3;
                ldsm4(b0, b1, b2, b3, VBu + (voff + p*640 + ks2*16)*2);
                uint32_t bA[2] = {b0, b1}, bB[2] = {b2, b3};
                mma16h(acc_o[2*p  ], a, bA);
                mma16h(acc_o[2*p+1], a, bB);
            }
        }
    }

    #pragma unroll
    for (int hf=0; hf<2; hf++){
        const float invl = 1.0f / l_r[hf];
        const int q = qbase + w*16 + hf*8 + lr;
        float* dst = g_attn + ((size_t)q*NBSZ + b)*EMB + h*HD;
        #pragma unroll
        for (int nt=0; nt<8; nt++)
            *(float2*)(dst + nt*8 + lc*2) =
                make_float2(rt(acc_o[nt][hf*2]*invl), rt(acc_o[nt][hf*2+1]*invl));
        if (lc == 0)
            g_stats[(size_t)bh*TGT + q] = make_float2(m_r[hf], invl);
    }
}

// ===========================================================================
// avg weights: 256 thr, block 128(q) x 64(k), warp tile 32x32, 2-stage ring.
// (unchanged — validated round 11)
// ===========================================================================
#define AVG_SMEM_BYTES (27648*4)

__global__ __launch_bounds__(256, 2)
void avg_attn_k(float* __restrict__ avg_out)
{
    extern __shared__ float sm[];
    const uint32_t sb = smem_u32(sm);
    const int tid = threadIdx.x, lane = tid & 31, wid = tid >> 5;
    const int wm = wid & 3, wn = wid >> 2;          // 4(q) x 2(k)
    const int lr = lane >> 2, lc = lane & 3;
    const int kt = blockIdx.x, qt = blockIdx.y, b = blockIdx.z;

    const uint32_t aoff = LDSM_A_OFF(lane, wm*32) * 4;
    const uint32_t boff = LDSM_B_OFF(lane, wn*32) * 4;

    auto issue_qk = [&](int h){
        const int st = h & 1;
        const int bh = b*NH + h;
        const float* Qg = g_Q + (size_t)bh*TGT*HD;
        const float* Kg = g_K + (size_t)bh*TGT*HD;
        const uint32_t qb = sb + (st*13824)*4;
        const uint32_t kb = sb + (st*13824 + 9216)*4;
        #pragma unroll
        for (int i=0;i<8;i++){
            int fi = tid + i*256, r = fi>>4, c4 = fi&15;
            cpa16(qb + ((c4>=8)*4608 + r*36 + (c4&7)*4)*4,
                  Qg + (size_t)(qt*128+r)*HD + c4*4);
        }
        #pragma unroll
        for (int i=0;i<4;i++){
            int fi = tid + i*256, r = fi>>4, c4 = fi&15;
            cpa16(kb + ((c4>=8)*2304 + r*36 + (c4&7)*4)*4,
                  Kg + (size_t)(kt*64+r)*HD + c4*4);
        }
        CP_COMMIT();
    };

    float acc[2][4][4];
    #pragma unroll
    for (int i=0;i<2;i++) for (int j=0;j<4;j++) for (int k=0;k<4;k++) acc[i][j][k]=0.f;

    issue_qk(0);
    for (int h = 0; h < NH; h++) {
        CP_WAIT(0);
        __syncthreads();
        if (h + 1 < NH) issue_qk(h+1);
        const int st = h & 1;
        const uint32_t QBu = sb + (st*13824)*4;
        const uint32_t KBu = sb + (st*13824 + 9216)*4;

        const int bh = b*NH + h;
        float crow[2][2];
        #pragma unroll
        for (int mt=0; mt<2; mt++)
        #pragma unroll
        for (int hf=0; hf<2; hf++){
            const int q = qt*128 + wm*32 + mt*16 + hf*8 + lr;
            const float2 st2 = g_stats[(size_t)bh*TGT + q];
            crow[mt][hf] = __log2f(st2.y) - st2.x * L2E;
        }

        float s[2][4][4];
        #pragma unroll
        for (int i=0;i<2;i++) for (int j=0;j<4;j++) for (int k=0;k<4;k++) s[i][j][k]=0.f;
        #pragma unroll
        for (int ks=0; ks<8; ks++){
            const int hb = ks>>2, ko = (ks&3)*8;
            uint32_t af[2][4], bf[4][2];
            #pragma unroll
            for (int mt=0; mt<2; mt++)
                ldsm4(af[mt][0], af[mt][1], af[mt][2], af[mt][3],
                      QBu + (hb*4608)*4 + aoff + (mt*576 + ko)*4);
            #pragma unroll
            for (int p=0; p<2; p++)
                ldsm4(bf[2*p][0], bf[2*p][1], bf[2*p+1][0], bf[2*p+1][1],
                      KBu + (hb*2304)*4 + boff + (p*576 + ko)*4);
            #pragma unroll
            for (int mt=0; mt<2; mt++)
                #pragma unroll
                for (int nt=0; nt<4; nt++)
                    mma8(s[mt][nt], af[mt], bf[nt]);
        }

        #pragma unroll
        for (int mt=0; mt<2; mt++)
        #pragma unroll
        for (int hf=0; hf<2; hf++){
            const float c = crow[mt][hf];
            #pragma unroll
            for (int nt=0; nt<4; nt++){
                acc[mt][nt][hf*2]   += exp2f(fmaf(s[mt][nt][hf*2],   L2E, c));
                acc[mt][nt][hf*2+1] += exp2f(fmaf(s[mt][nt][hf*2+1], L2E, c));
            }
        }
    }

    const float invH = 1.0f / NH;
    #pragma unroll
    for (int mt=0; mt<2; mt++)
    #pragma unroll
    for (int hf=0; hf<2; hf++){
        const int q = qt*128 + wm*32 + mt*16 + hf*8 + lr;
        float* dst = avg_out + ((size_t)b*TGT + q)*TGT + kt*64 + wn*32;
        #pragma unroll
        for (int nt=0; nt<4; nt++)
            *(float2*)(dst + nt*8 + lc*2) =
                make_float2(acc[mt][nt][hf*2]*invH, acc[mt][nt][hf*2+1]*invH);
    }
}

// ---------------------------------------------------------------------------
extern "C" void kernel_launch(void* const* d_in, const int* in_sizes, int n_in,
                              void* d_out, int out_size)
{
    const float* query = (const float*)d_in[0];
    const float* w_in  = (const float*)d_in[1];
    const float* b_in  = (const float*)d_in[2];
    const float* w_out = (const float*)d_in[3];
    const float* b_out = (const float*)d_in[4];

    float* out      = (float*)d_out;
    float* attn_out = out;                           // [T,B,E]
    float* avg_out  = out + (size_t)TGT*NBSZ*EMB;    // [B,T,T]

    cudaFuncSetAttribute(mma_gemm<0>,  cudaFuncAttributeMaxDynamicSharedMemorySize, GEMM_SMEM_BYTES);
    cudaFuncSetAttribute(mma_gemm<3>,  cudaFuncAttributeMaxDynamicSharedMemorySize, GEMM_SMEM_BYTES);
    cudaFuncSetAttribute(flash_attn_k, cudaFuncAttributeMaxDynamicSharedMemorySize, FA_SMEM_BYTES);
    cudaFuncSetAttribute(avg_attn_k,   cudaFuncAttributeMaxDynamicSharedMemorySize, AVG_SMEM_BYTES);

    float* d_qc;  cudaGetSymbolAddress((void**)&d_qc,  g_qc);
    float* d_wic; cudaGetSymbolAddress((void**)&d_wic, g_wic);
    float* d_woc; cudaGetSymbolAddress((void**)&d_woc, g_woc);

    // 0. pre-round inputs to tf32 (single launch)
    {
        int total = MROWS*EMB/4 + 3*EMB*EMB/4 + EMB*EMB/4;
        preround_all_k<<<(total+255)/256, 256>>>(
            (const float4*)query, (const float4*)w_in, (const float4*)w_out,
            (float4*)d_qc, (float4*)d_wic, (float4*)d_woc);
    }

    // 1. QKV projection
    mma_gemm<0><<<dim3(3*EMB/128, MROWS/128), 256, GEMM_SMEM_BYTES>>>(nullptr, b_in);

    // 2. Flash attention (fp16 PV)
    flash_attn_k<<<dim3(TGT/128, NBH), 256, FA_SMEM_BYTES>>>();

    // 3. Averaged attention weights
    avg_attn_k<<<dim3(TGT/64, TGT/128, NBSZ), 256, AVG_SMEM_BYTES>>>(avg_out);

    // 4. Output projection
    mma_gemm<3><<<dim3(EMB/128, MROWS/128), 256, GEMM_SMEM_BYTES>>>(attn_out, b_out);
}

// round 13
// speedup vs baseline: 2.0090x; 1.5624x over previous
#include <cuda_runtime.h>
#include <cuda_fp16.h>
#include <cstdint>
#include <math.h>

#define TGT   2048
#define NBSZ  2
#define EMB   1024
#define NH    16
#define HD    64
#define NBH   (NBSZ*NH)      // 32
#define MROWS (TGT*NBSZ)     // 4096

// ---------------- scratch (device globals, all fp16 operands) ---------------
static __device__ __half g_Qh [(size_t)NBH*TGT*HD];     // pre-scaled
static __device__ __half g_Kh [(size_t)NBH*TGT*HD];
static __device__ __half g_Vt [(size_t)NBH*HD*TGT];     // [bh][d][t]
static __device__ __half g_attnh[(size_t)MROWS*EMB];
static __device__ float2 g_stats[(size_t)NBH*TGT];      // (rowmax, 1/rowsum)
static __device__ __half g_qh [(size_t)MROWS*EMB];
static __device__ __half g_wih[(size_t)3*EMB*EMB];
static __device__ __half g_woh[(size_t)EMB*EMB];

// ---------------- helpers ---------------------------------------------------
__device__ __forceinline__ uint32_t pack_h2(float hi, float lo){
    uint32_t r; asm("cvt.rn.f16x2.f32 %0, %1, %2;" : "=r"(r) : "f"(hi), "f"(lo));
    return r;
}
__device__ __forceinline__ void mma16h(float* c, const uint32_t* a, const uint32_t* b){
    asm volatile("mma.sync.aligned.m16n8k16.row.col.f32.f16.f16.f32 "
        "{%0,%1,%2,%3}, {%4,%5,%6,%7}, {%8,%9}, {%0,%1,%2,%3};"
        : "+f"(c[0]), "+f"(c[1]), "+f"(c[2]), "+f"(c[3])
        : "r"(a[0]), "r"(a[1]), "r"(a[2]), "r"(a[3]), "r"(b[0]), "r"(b[1]));
}
__device__ __forceinline__ void ldsm4(uint32_t& r0, uint32_t& r1, uint32_t& r2,
                                      uint32_t& r3, uint32_t addr){
    asm volatile("ldmatrix.sync.aligned.m8n8.x4.shared.b16 {%0,%1,%2,%3}, [%4];"
        : "=r"(r0), "=r"(r1), "=r"(r2), "=r"(r3) : "r"(addr));
}
__device__ __forceinline__ uint32_t smem_u32(const void* p){
    uint32_t a; asm("{ .reg .u64 t; cvta.to.shared.u64 t, %1; cvt.u32.u64 %0, t; }":"=r"(a):"l"(p));
    return a;
}
__device__ __forceinline__ void cpa16(uint32_t s, const void* g){
    asm volatile("cp.async.cg.shared.global [%0], [%1], 16;" :: "r"(s), "l"(g) : "memory");
}
#define CP_COMMIT() asm volatile("cp.async.commit_group;" ::: "memory")
#define CP_WAIT(n)  asm volatile("cp.async.wait_group %0;" :: "n"(n) : "memory")

// fp16 ldmatrix lane->offset (in HALFS) for m16n8k16 fragments.
// A (16 rows x 16 k): mats (r0-7,k0-7)(r8-15,k0-7)(r0-7,k8-15)(r8-15,k8-15)
#define LDSM_H_A(j, rowbase, stride) \
    ((((rowbase) + (((j)>>3)&1)*8 + ((j)&7))*(stride)) + (((j)>>4)*8))
// B pair (2 n-tiles x 16 k): mats (nt0,k0-7)(nt0,k8-15)(nt1,k0-7)(nt1,k8-15)
#define LDSM_H_B(j, rowbase, stride) \
    ((((rowbase) + (((j)>>4)*8) + ((j)&7))*(stride)) + ((((j)>>3)&1)*8))

#define L2E 1.4426950408889634f

// ---------------- fused pre-convert fp32 -> fp16 (one launch) ---------------
__global__ void preconv_all_k(const float4* __restrict__ q,
                              const float4* __restrict__ wi,
                              const float4* __restrict__ wo,
                              uint2* __restrict__ dq,
                              uint2* __restrict__ dwi,
                              uint2* __restrict__ dwo)
{
    const int NQ = MROWS*EMB/4, NWI = 3*EMB*EMB/4, NWO = EMB*EMB/4;
    int i = blockIdx.x*blockDim.x + threadIdx.x;
    float4 v; uint2 o;
    if (i < NQ)              { v = q[i];        o.x = pack_h2(v.y, v.x); o.y = pack_h2(v.w, v.z); dq[i] = o; }
    else if (i < NQ+NWI)     { v = wi[i-NQ];    o.x = pack_h2(v.y, v.x); o.y = pack_h2(v.w, v.z); dwi[i-NQ] = o; }
    else if (i < NQ+NWI+NWO) { v = wo[i-NQ-NWI];o.x = pack_h2(v.y, v.x); o.y = pack_h2(v.w, v.z); dwo[i-NQ-NWI] = o; }
}

// ===========================================================================
// Projection GEMMs (fp16): block 128x128, 256 thr, warp 64x32, BK=64, 3-stage.
// SMEM halfs: stage st @ st*18432: A (128x72=9216) + B (9216). 110592 B total.
// MODE 0: QKV -> g_Qh/g_Kh/g_Vt (fp16).  MODE 3: out-proj -> fp32 Cg + bias.
// ===========================================================================
#define GEMM_SMEM_BYTES (3*18432*2)   // 110592

template<int MODE>
__global__ __launch_bounds__(256, 2)
void mma_gemm(float* __restrict__ Cg, const float* __restrict__ biasg)
{
    constexpr int KC = 16;            // 1024 / 64
    extern __shared__ char smc[];
    const uint32_t sb = smem_u32(smc);
    const int tid = threadIdx.x, lane = tid & 31, wid = tid >> 5;
    const int wm = wid & 1, wn = wid >> 1;          // 2(m) x 4(n)
    const int lr = lane >> 2, lc = lane & 3;
    const int bm = blockIdx.y * 128, bn = blockIdx.x * 128;

    const __half* A = (MODE == 0) ? g_qh  : g_attnh;
    const __half* B = (MODE == 0) ? g_wih : g_woh;

    const uint32_t aoff = LDSM_H_A(lane, wm*64, 72);
    const uint32_t boff = LDSM_H_B(lane, wn*32, 72);

    float acc[4][4][4];
    #pragma unroll
    for (int i=0;i<4;i++) for (int j=0;j<4;j++) for (int k=0;k<4;k++) acc[i][j][k]=0.f;

    auto issue = [&](int c){
        const int k0 = c*64, st = c % 3;
        const uint32_t ab = sb + st*36864;
        const uint32_t bb = ab + 18432;
        #pragma unroll
        for (int i=0;i<4;i++){
            int fi = tid + i*256, r = fi>>3, c8 = fi&7;
            cpa16(ab + (r*72 + c8*8)*2, A + (size_t)(bm+r)*EMB + k0 + c8*8);
            cpa16(bb + (r*72 + c8*8)*2, B + (size_t)(bn+r)*EMB + k0 + c8*8);
        }
        CP_COMMIT();
    };

    issue(0); issue(1);
    for (int c = 0; c < KC; c++) {
        if (c + 1 < KC) { CP_WAIT(1); } else { CP_WAIT(0); }
        __syncthreads();
        if (c + 2 < KC) issue(c+2);
        const int st = c % 3;
        const uint32_t Ab = sb + st*36864;
        const uint32_t Bb = Ab + 18432;
        #pragma unroll
        for (int ks = 0; ks < 4; ks++) {
            uint32_t af[4][4], bf[4][2];
            #pragma unroll
            for (int mt=0; mt<4; mt++)
                ldsm4(af[mt][0], af[mt][1], af[mt][2], af[mt][3],
                      Ab + (aoff + mt*16*72 + ks*16)*2);
            #pragma unroll
            for (int p=0; p<2; p++)
                ldsm4(bf[2*p][0], bf[2*p][1], bf[2*p+1][0], bf[2*p+1][1],
                      Bb + (boff + p*16*72 + ks*16)*2);
            #pragma unroll
            for (int mt=0; mt<4; mt++)
                #pragma unroll
                for (int nt=0; nt<4; nt++)
                    mma16h(acc[mt][nt], af[mt], bf[nt]);
        }
    }

    float bias0[4], bias1[4];
    #pragma unroll
    for (int nt=0; nt<4; nt++){
        int n = bn + wn*32 + nt*8 + lc*2;
        bias0[nt] = biasg[n]; bias1[nt] = biasg[n+1];
    }

    #pragma unroll
    for (int mt=0; mt<4; mt++)
    #pragma unroll
    for (int hf=0; hf<2; hf++){
        const int m = bm + wm*64 + mt*16 + hf*8 + lr;
        if (MODE == 0) {
            const int t = m >> 1, b = m & 1;
            #pragma unroll
            for (int nt=0; nt<4; nt++){
                const int n = bn + wn*32 + nt*8 + lc*2;
                float v0 = acc[mt][nt][hf*2+0] + bias0[nt];
                float v1 = acc[mt][nt][hf*2+1] + bias1[nt];
                const int which = n >> 10, e = n & 1023, h = e >> 6, d = e & 63;
                const int bh = b*NH + h;
                if (which == 0) {
                    *(uint32_t*)&g_Qh[((size_t)bh*TGT + t)*HD + d] =
                        pack_h2(v1*0.125f, v0*0.125f);
                } else if (which == 1) {
                    *(uint32_t*)&g_Kh[((size_t)bh*TGT + t)*HD + d] = pack_h2(v1, v0);
                } else {
                    g_Vt[((size_t)bh*HD + d    )*TGT + t] = __float2half(v0);
                    g_Vt[((size_t)bh*HD + d + 1)*TGT + t] = __float2half(v1);
                }
            }
        } else {
            float* dst = Cg + (size_t)m*EMB;
            #pragma unroll
            for (int nt=0; nt<4; nt++){
                const int n = bn + wn*32 + nt*8 + lc*2;
                *(float2*)&dst[n] = make_float2(acc[mt][nt][hf*2] + bias0[nt],
                                                acc[mt][nt][hf*2+1] + bias1[nt]);
            }
        }
    }
}

// ===========================================================================
// Flash attention (full fp16): 256 thr, q-tile 128 (warp=16 rows), k-chunk 32.
// 4-stage KV ring, prefetch 3. S via mma16h; PV zero-shuffle (round 12).
// SMEM: Q@0 (9216 h = 18432 B); stage st @ 18432+st*9728:
//   K 32x72h (4608 B) + V 64x40h (5120 B).  Total 57344 B.
// ===========================================================================
#define FA_SMEM_BYTES (18432 + 4*9728)   // 57344

__global__ __launch_bounds__(256, 2)
void flash_attn_k()
{
    constexpr int NC = TGT/32;          // 64 chunks
    extern __shared__ char smc[];
    const uint32_t sb = smem_u32(smc);
    const int tid = threadIdx.x, lane = tid & 31, w = tid >> 5;
    const int lr = lane >> 2, lc = lane & 3;
    const int qt = blockIdx.x, bh = blockIdx.y;
    const int b = bh >> 4, h = bh & 15;
    const int qbase = qt * 128;

    const __half* Qg = g_Qh + (size_t)bh*TGT*HD;
    const __half* Kg = g_Kh + (size_t)bh*TGT*HD;
    const __half* Vg = g_Vt + (size_t)bh*HD*TGT;

    const uint32_t qoff = LDSM_H_A(lane, w*16, 72);
    const uint32_t koff = LDSM_H_B(lane, 0, 72);
    const uint32_t voff = LDSM_H_B(lane, 0, 40);

    auto issue_kv = [&](int kc){
        const int st = kc & 3;
        const uint32_t kb = sb + 18432 + st*9728;
        const uint32_t vb = kb + 4608;
        {   // K: 32 rows x 64 halfs, 1 cpa/thread
            int r = tid >> 3, c8 = tid & 7;
            cpa16(kb + (r*72 + c8*8)*2, Kg + (size_t)(kc*32+r)*HD + c8*8);
        }
        {   // V: 64 d-rows x 32 t-cols, 1 cpa/thread
            int d = tid >> 2, c4 = tid & 3;
            cpa16(vb + (d*40 + c4*8)*2, Vg + (size_t)d*TGT + kc*32 + c4*8);
        }
        CP_COMMIT();
    };

    // prologue: group0 = Q + KV0; then KV1, KV2
    #pragma unroll
    for (int i=0;i<4;i++){
        int fi = tid + i*256, r = fi>>3, c8 = fi&7;
        cpa16(sb + (r*72 + c8*8)*2, Qg + (size_t)(qbase+r)*HD + c8*8);
    }
    {
        const uint32_t kb = sb + 18432, vb = kb + 4608;
        int r = tid >> 3, c8 = tid & 7;
        cpa16(kb + (r*72 + c8*8)*2, Kg + (size_t)r*HD + c8*8);
        int d = tid >> 2, c4 = tid & 3;
        cpa16(vb + (d*40 + c4*8)*2, Vg + (size_t)d*TGT + c4*8);
        CP_COMMIT();
    }
    issue_kv(1); issue_kv(2);

    float acc_o[8][4];
    #pragma unroll
    for (int j=0;j<8;j++) for (int k=0;k<4;k++) acc_o[j][k]=0.f;
    float m_r[2] = {-1e30f,-1e30f};
    float l_r[2] = {0.f,0.f};

    const unsigned FULL = 0xffffffffu;

    for (int kc = 0; kc < NC; kc++) {
        if (kc + 2 < NC)      { CP_WAIT(2); }
        else if (kc + 1 < NC) { CP_WAIT(1); }
        else                  { CP_WAIT(0); }
        __syncthreads();
        if (kc + 3 < NC) issue_kv(kc + 3);

        const int st = kc & 3;
        const uint32_t KBu = sb + 18432 + st*9728;
        const uint32_t VBu = KBu + 4608;

        // S = Q K^T  (128q x 32k chunk, fp16 k16)
        float s[4][4];
        #pragma unroll
        for (int j=0;j<4;j++) for (int k=0;k<4;k++) s[j][k]=0.f;
        #pragma unroll
        for (int ks=0; ks<4; ks++){
            uint32_t a[4], bf[4][2];
            ldsm4(a[0], a[1], a[2], a[3], sb + (qoff + ks*16)*2);
            #pragma unroll
            for (int p=0; p<2; p++)
                ldsm4(bf[2*p][0], bf[2*p][1], bf[2*p+1][0], bf[2*p+1][1],
                      KBu + (koff + p*16*72 + ks*16)*2);
            #pragma unroll
            for (int nt=0; nt<4; nt++)
                mma16h(s[nt], a, bf[nt]);
        }

        // online softmax over this 32-col chunk
        #pragma unroll
        for (int hf=0; hf<2; hf++){
            float cm = -1e30f;
            #pragma unroll
            for (int nt=0; nt<4; nt++)
                cm = fmaxf(cm, fmaxf(s[nt][hf*2], s[nt][hf*2+1]));
            cm = fmaxf(cm, __shfl_xor_sync(FULL, cm, 1));
            cm = fmaxf(cm, __shfl_xor_sync(FULL, cm, 2));
            const float mn = fmaxf(m_r[hf], cm);
            const float sc = __expf(m_r[hf] - mn);
            float cs = 0.f;
            #pragma unroll
            for (int nt=0; nt<4; nt++){
                float e0 = __expf(s[nt][hf*2]   - mn);
                float e1 = __expf(s[nt][hf*2+1] - mn);
                s[nt][hf*2] = e0; s[nt][hf*2+1] = e1;
                cs += e0 + e1;
            }
            cs += __shfl_xor_sync(FULL, cs, 1);
            cs += __shfl_xor_sync(FULL, cs, 2);
            l_r[hf] = l_r[hf]*sc + cs;
            m_r[hf] = mn;
            #pragma unroll
            for (int nt=0; nt<4; nt++){
                acc_o[nt][hf*2]     *= sc;
                acc_o[nt][hf*2+1]   *= sc;
                acc_o[nt+4][hf*2]   *= sc;
                acc_o[nt+4][hf*2+1] *= sc;
            }
        }

        // O += P V  (fp16, A-frags packed straight from S C-frags)
        #pragma unroll
        for (int ks2=0; ks2<2; ks2++){
            uint32_t a[4];
            a[0] = pack_h2(s[2*ks2  ][1], s[2*ks2  ][0]);
            a[1] = pack_h2(s[2*ks2  ][3], s[2*ks2  ][2]);
            a[2] = pack_h2(s[2*ks2+1][1], s[2*ks2+1][0]);
            a[3] = pack_h2(s[2*ks2+1][3], s[2*ks2+1][2]);
            #pragma unroll
            for (int p=0; p<4; p++){
                uint32_t b0, b1, b2, b3;
                ldsm4(b0, b1, b2, b3, VBu + (voff + p*640 + ks2*16)*2);
                uint32_t bA[2] = {b0, b1}, bB[2] = {b2, b3};
                mma16h(acc_o[2*p  ], a, bA);
                mma16h(acc_o[2*p+1], a, bB);
            }
        }
    }

    #pragma unroll
    for (int hf=0; hf<2; hf++){
        const float invl = 1.0f / l_r[hf];
        const int q = qbase + w*16 + hf*8 + lr;
        __half* dst = g_attnh + ((size_t)q*NBSZ + b)*EMB + h*HD;
        #pragma unroll
        for (int nt=0; nt<8; nt++)
            *(uint32_t*)&dst[nt*8 + lc*2] =
                pack_h2(acc_o[nt][hf*2+1]*invl, acc_o[nt][hf*2]*invl);
        if (lc == 0)
            g_stats[(size_t)bh*TGT + q] = make_float2(m_r[hf], invl);
    }
}

// ===========================================================================
// avg weights (fp16 S): 256 thr, block 128(q) x 64(k), warp 32x32, 2-stage.
// SMEM halfs: stage st @ st*13824: Q (9216) + K (4608). 55296 B total.
// ===========================================================================
#define AVG_SMEM_BYTES (2*13824*2)   // 55296

__global__ __launch_bounds__(256, 2)
void avg_attn_k(float* __restrict__ avg_out)
{
    extern __shared__ char smc[];
    const uint32_t sb = smem_u32(smc);
    const int tid = threadIdx.x, lane = tid & 31, wid = tid >> 5;
    const int wm = wid & 3, wn = wid >> 2;          // 4(q) x 2(k)
    const int lr = lane >> 2, lc = lane & 3;
    const int kt = blockIdx.x, qt = blockIdx.y, b = blockIdx.z;

    const uint32_t aoff = LDSM_H_A(lane, wm*32, 72);
    const uint32_t boff = LDSM_H_B(lane, wn*32, 72);

    auto issue_qk = [&](int h){
        const int st = h & 1;
        const int bh = b*NH + h;
        const __half* Qg = g_Qh + (size_t)bh*TGT*HD;
        const __half* Kg = g_Kh + (size_t)bh*TGT*HD;
        const uint32_t qb = sb + st*27648;
        const uint32_t kb = qb + 18432;
        #pragma unroll
        for (int i=0;i<4;i++){
            int fi = tid + i*256, r = fi>>3, c8 = fi&7;
            cpa16(qb + (r*72 + c8*8)*2, Qg + (size_t)(qt*128+r)*HD + c8*8);
        }
        #pragma unroll
        for (int i=0;i<2;i++){
            int fi = tid + i*256, r = fi>>3, c8 = fi&7;
            cpa16(kb + (r*72 + c8*8)*2, Kg + (size_t)(kt*64+r)*HD + c8*8);
        }
        CP_COMMIT();
    };

    float acc[2][4][4];
    #pragma unroll
    for (int i=0;i<2;i++) for (int j=0;j<4;j++) for (int k=0;k<4;k++) acc[i][j][k]=0.f;

    issue_qk(0);
    for (int h = 0; h < NH; h++) {
        CP_WAIT(0);
        __syncthreads();
        if (h + 1 < NH) issue_qk(h+1);
        const int st = h & 1;
        const uint32_t QBu = sb + st*27648;
        const uint32_t KBu = QBu + 18432;

        const int bh = b*NH + h;
        float crow[2][2];
        #pragma unroll
        for (int mt=0; mt<2; mt++)
        #pragma unroll
        for (int hf=0; hf<2; hf++){
            const int q = qt*128 + wm*32 + mt*16 + hf*8 + lr;
            const float2 st2 = g_stats[(size_t)bh*TGT + q];
            crow[mt][hf] = __log2f(st2.y) - st2.x * L2E;
        }

        float s[2][4][4];
        #pragma unroll
        for (int i=0;i<2;i++) for (int j=0;j<4;j++) for (int k=0;k<4;k++) s[i][j][k]=0.f;
        #pragma unroll
        for (int ks=0; ks<4; ks++){
            uint32_t af[2][4], bf[4][2];
            #pragma unroll
            for (int mt=0; mt<2; mt++)
                ldsm4(af[mt][0], af[mt][1], af[mt][2], af[mt][3],
                      QBu + (aoff + mt*16*72 + ks*16)*2);
            #pragma unroll
            for (int p=0; p<2; p++)
                ldsm4(bf[2*p][0], bf[2*p][1], bf[2*p+1][0], bf[2*p+1][1],
                      KBu + (boff + p*16*72 + ks*16)*2);
            #pragma unroll
            for (int mt=0; mt<2; mt++)
                #pragma unroll
                for (int nt=0; nt<4; nt++)
                    mma16h(s[mt][nt], af[mt], bf[nt]);
        }

        #pragma unroll
        for (int mt=0; mt<2; mt++)
        #pragma unroll
        for (int hf=0; hf<2; hf++){
            const float c = crow[mt][hf];
            #pragma unroll
            for (int nt=0; nt<4; nt++){
                acc[mt][nt][hf*2]   += exp2f(fmaf(s[mt][nt][hf*2],   L2E, c));
                acc[mt][nt][hf*2+1] += exp2f(fmaf(s[mt][nt][hf*2+1], L2E, c));
            }
        }
    }

    const float invH = 1.0f / NH;
    #pragma unroll
    for (int mt=0; mt<2; mt++)
    #pragma unroll
    for (int hf=0; hf<2; hf++){
        const int q = qt*128 + wm*32 + mt*16 + hf*8 + lr;
        float* dst = avg_out + ((size_t)b*TGT + q)*TGT + kt*64 + wn*32;
        #pragma unroll
        for (int nt=0; nt<4; nt++)
            *(float2*)(dst + nt*8 + lc*2) =
                make_float2(acc[mt][nt][hf*2]*invH, acc[mt][nt][hf*2+1]*invH);
    }
}

// ---------------------------------------------------------------------------
extern "C" void kernel_launch(void* const* d_in, const int* in_sizes, int n_in,
                              void* d_out, int out_size)
{
    const float* query = (const float*)d_in[0];
    const float* w_in  = (const float*)d_in[1];
    const float* b_in  = (const float*)d_in[2];
    const float* w_out = (const float*)d_in[3];
    const float* b_out = (const float*)d_in[4];

    float* out      = (float*)d_out;
    float* attn_out = out;                           // [T,B,E]
    float* avg_out  = out + (size_t)TGT*NBSZ*EMB;    // [B,T,T]

    cudaFuncSetAttribute(mma_gemm<0>,  cudaFuncAttributeMaxDynamicSharedMemorySize, GEMM_SMEM_BYTES);
    cudaFuncSetAttribute(mma_gemm<3>,  cudaFuncAttributeMaxDynamicSharedMemorySize, GEMM_SMEM_BYTES);
    cudaFuncSetAttribute(flash_attn_k, cudaFuncAttributeMaxDynamicSharedMemorySize, FA_SMEM_BYTES);
    cudaFuncSetAttribute(avg_attn_k,   cudaFuncAttributeMaxDynamicSharedMemorySize, AVG_SMEM_BYTES);

    __half* d_qh;  cudaGetSymbolAddress((void**)&d_qh,  g_qh);
    __half* d_wih; cudaGetSymbolAddress((void**)&d_wih, g_wih);
    __half* d_woh; cudaGetSymbolAddress((void**)&d_woh, g_woh);

    // 0. fp32 -> fp16 convert (single launch)
    {
        int total = MROWS*EMB/4 + 3*EMB*EMB/4 + EMB*EMB/4;
        preconv_all_k<<<(total+255)/256, 256>>>(
            (const float4*)query, (const float4*)w_in, (const float4*)w_out,
            (uint2*)d_qh, (uint2*)d_wih, (uint2*)d_woh);
    }

    // 1. QKV projection (fp16)
    mma_gemm<0><<<dim3(3*EMB/128, MROWS/128), 256, GEMM_SMEM_BYTES>>>(nullptr, b_in);

    // 2. Flash attention (fp16)
    flash_attn_k<<<dim3(TGT/128, NBH), 256, FA_SMEM_BYTES>>>();

    // 3. Averaged attention weights (fp16 S)
    avg_attn_k<<<dim3(TGT/64, TGT/128, NBSZ), 256, AVG_SMEM_BYTES>>>(avg_out);

    // 4. Output projection (fp16 in, fp32 out)
    mma_gemm<3><<<dim3(EMB/128, MROWS/128), 256, GEMM_SMEM_BYTES>>>(attn_out, b_out);
}

// round 14
// speedup vs baseline: 2.1550x; 1.0727x over previous
#include <cuda_runtime.h>
#include <cuda_fp16.h>
#include <cstdint>
#include <math.h>

#define TGT   2048
#define NBSZ  2
#define EMB   1024
#define NH    16
#define HD    64
#define NBH   (NBSZ*NH)      // 32
#define MROWS (TGT*NBSZ)     // 4096

// ---------------- scratch (device globals, all fp16 operands) ---------------
static __device__ __half g_Qh [(size_t)NBH*TGT*HD];     // pre-scaled
static __device__ __half g_Kh [(size_t)NBH*TGT*HD];
static __device__ __half g_Vh [(size_t)NBH*TGT*HD];     // [bh][t][d] (row-major!)
static __device__ __half g_attnh[(size_t)MROWS*EMB];
static __device__ float2 g_stats[(size_t)NBH*TGT];      // (rowmax, 1/rowsum)
static __device__ __half g_qh [(size_t)MROWS*EMB];
static __device__ __half g_wih[(size_t)3*EMB*EMB];
static __device__ __half g_woh[(size_t)EMB*EMB];

// ---------------- helpers ---------------------------------------------------
__device__ __forceinline__ uint32_t pack_h2(float hi, float lo){
    uint32_t r; asm("cvt.rn.f16x2.f32 %0, %1, %2;" : "=r"(r) : "f"(hi), "f"(lo));
    return r;
}
__device__ __forceinline__ void mma16h(float* c, const uint32_t* a, const uint32_t* b){
    asm volatile("mma.sync.aligned.m16n8k16.row.col.f32.f16.f16.f32 "
        "{%0,%1,%2,%3}, {%4,%5,%6,%7}, {%8,%9}, {%0,%1,%2,%3};"
        : "+f"(c[0]), "+f"(c[1]), "+f"(c[2]), "+f"(c[3])
        : "r"(a[0]), "r"(a[1]), "r"(a[2]), "r"(a[3]), "r"(b[0]), "r"(b[1]));
}
__device__ __forceinline__ void ldsm4(uint32_t& r0, uint32_t& r1, uint32_t& r2,
                                      uint32_t& r3, uint32_t addr){
    asm volatile("ldmatrix.sync.aligned.m8n8.x4.shared.b16 {%0,%1,%2,%3}, [%4];"
        : "=r"(r0), "=r"(r1), "=r"(r2), "=r"(r3) : "r"(addr));
}
__device__ __forceinline__ void ldsm4t(uint32_t& r0, uint32_t& r1, uint32_t& r2,
                                       uint32_t& r3, uint32_t addr){
    asm volatile("ldmatrix.sync.aligned.m8n8.x4.trans.shared.b16 {%0,%1,%2,%3}, [%4];"
        : "=r"(r0), "=r"(r1), "=r"(r2), "=r"(r3) : "r"(addr));
}
__device__ __forceinline__ uint32_t smem_u32(const void* p){
    uint32_t a; asm("{ .reg .u64 t; cvta.to.shared.u64 t, %1; cvt.u32.u64 %0, t; }":"=r"(a):"l"(p));
    return a;
}
__device__ __forceinline__ void cpa16(uint32_t s, const void* g){
    asm volatile("cp.async.cg.shared.global [%0], [%1], 16;" :: "r"(s), "l"(g) : "memory");
}
#define CP_COMMIT() asm volatile("cp.async.commit_group;" ::: "memory")
#define CP_WAIT(n)  asm volatile("cp.async.wait_group %0;" :: "n"(n) : "memory")

// fp16 ldmatrix lane->offset (in HALFS) for m16n8k16 fragments.
// A (16 rows x 16 k): mats (r0-7,k0-7)(r8-15,k0-7)(r0-7,k8-15)(r8-15,k8-15)
#define LDSM_H_A(j, rowbase, stride) \
    ((((rowbase) + (((j)>>3)&1)*8 + ((j)&7))*(stride)) + (((j)>>4)*8))
// B pair (2 n-tiles x 16 k): mats (nt0,k0-7)(nt0,k8-15)(nt1,k0-7)(nt1,k8-15)
#define LDSM_H_B(j, rowbase, stride) \
    ((((rowbase) + (((j)>>4)*8) + ((j)&7))*(stride)) + ((((j)>>3)&1)*8))

#define L2E 1.4426950408889634f

// ---------------- fused pre-convert fp32 -> fp16 (one launch) ---------------
__global__ void preconv_all_k(const float4* __restrict__ q,
                              const float4* __restrict__ wi,
                              const float4* __restrict__ wo,
                              uint2* __restrict__ dq,
                              uint2* __restrict__ dwi,
                              uint2* __restrict__ dwo)
{
    const int NQ = MROWS*EMB/4, NWI = 3*EMB*EMB/4, NWO = EMB*EMB/4;
    int i = blockIdx.x*blockDim.x + threadIdx.x;
    float4 v; uint2 o;
    if (i < NQ)              { v = q[i];        o.x = pack_h2(v.y, v.x); o.y = pack_h2(v.w, v.z); dq[i] = o; }
    else if (i < NQ+NWI)     { v = wi[i-NQ];    o.x = pack_h2(v.y, v.x); o.y = pack_h2(v.w, v.z); dwi[i-NQ] = o; }
    else if (i < NQ+NWI+NWO) { v = wo[i-NQ-NWI];o.x = pack_h2(v.y, v.x); o.y = pack_h2(v.w, v.z); dwo[i-NQ-NWI] = o; }
}

// ===========================================================================
// Projection GEMMs (fp16): block 128x128, 256 thr, warp 64x32, BK=64, 3-stage.
// SMEM halfs: stage st @ st*18432: A (128x72=9216) + B (9216). 110592 B total.
// MODE 0: QKV -> g_Qh/g_Kh/g_Vh (all row-major now).  MODE 3: out-proj.
// ===========================================================================
#define GEMM_SMEM_BYTES (3*18432*2)   // 110592

template<int MODE>
__global__ __launch_bounds__(256, 2)
void mma_gemm(float* __restrict__ Cg, const float* __restrict__ biasg)
{
    constexpr int KC = 16;            // 1024 / 64
    extern __shared__ char smc[];
    const uint32_t sb = smem_u32(smc);
    const int tid = threadIdx.x, lane = tid & 31, wid = tid >> 5;
    const int wm = wid & 1, wn = wid >> 1;          // 2(m) x 4(n)
    const int lr = lane >> 2, lc = lane & 3;
    const int bm = blockIdx.y * 128, bn = blockIdx.x * 128;

    const __half* A = (MODE == 0) ? g_qh  : g_attnh;
    const __half* B = (MODE == 0) ? g_wih : g_woh;

    const uint32_t aoff = LDSM_H_A(lane, wm*64, 72);
    const uint32_t boff = LDSM_H_B(lane, wn*32, 72);

    float acc[4][4][4];
    #pragma unroll
    for (int i=0;i<4;i++) for (int j=0;j<4;j++) for (int k=0;k<4;k++) acc[i][j][k]=0.f;

    auto issue = [&](int c){
        const int k0 = c*64, st = c % 3;
        const uint32_t ab = sb + st*36864;
        const uint32_t bb = ab + 18432;
        #pragma unroll
        for (int i=0;i<4;i++){
            int fi = tid + i*256, r = fi>>3, c8 = fi&7;
            cpa16(ab + (r*72 + c8*8)*2, A + (size_t)(bm+r)*EMB + k0 + c8*8);
            cpa16(bb + (r*72 + c8*8)*2, B + (size_t)(bn+r)*EMB + k0 + c8*8);
        }
        CP_COMMIT();
    };

    issue(0); issue(1);
    for (int c = 0; c < KC; c++) {
        if (c + 1 < KC) { CP_WAIT(1); } else { CP_WAIT(0); }
        __syncthreads();
        if (c + 2 < KC) issue(c+2);
        const int st = c % 3;
        const uint32_t Ab = sb + st*36864;
        const uint32_t Bb = Ab + 18432;
        #pragma unroll
        for (int ks = 0; ks < 4; ks++) {
            uint32_t af[4][4], bf[4][2];
            #pragma unroll
            for (int mt=0; mt<4; mt++)
                ldsm4(af[mt][0], af[mt][1], af[mt][2], af[mt][3],
                      Ab + (aoff + mt*16*72 + ks*16)*2);
            #pragma unroll
            for (int p=0; p<2; p++)
                ldsm4(bf[2*p][0], bf[2*p][1], bf[2*p+1][0], bf[2*p+1][1],
                      Bb + (boff + p*16*72 + ks*16)*2);
            #pragma unroll
            for (int mt=0; mt<4; mt++)
                #pragma unroll
                for (int nt=0; nt<4; nt++)
                    mma16h(acc[mt][nt], af[mt], bf[nt]);
        }
    }

    float bias0[4], bias1[4];
    #pragma unroll
    for (int nt=0; nt<4; nt++){
        int n = bn + wn*32 + nt*8 + lc*2;
        bias0[nt] = biasg[n]; bias1[nt] = biasg[n+1];
    }

    #pragma unroll
    for (int mt=0; mt<4; mt++)
    #pragma unroll
    for (int hf=0; hf<2; hf++){
        const int m = bm + wm*64 + mt*16 + hf*8 + lr;
        if (MODE == 0) {
            const int t = m >> 1, b = m & 1;
            #pragma unroll
            for (int nt=0; nt<4; nt++){
                const int n = bn + wn*32 + nt*8 + lc*2;
                float v0 = acc[mt][nt][hf*2+0] + bias0[nt];
                float v1 = acc[mt][nt][hf*2+1] + bias1[nt];
                const int which = n >> 10, e = n & 1023, h = e >> 6, d = e & 63;
                const int bh = b*NH + h;
                if (which == 0) {
                    *(uint32_t*)&g_Qh[((size_t)bh*TGT + t)*HD + d] =
                        pack_h2(v1*0.125f, v0*0.125f);
                } else if (which == 1) {
                    *(uint32_t*)&g_Kh[((size_t)bh*TGT + t)*HD + d] = pack_h2(v1, v0);
                } else {
                    *(uint32_t*)&g_Vh[((size_t)bh*TGT + t)*HD + d] = pack_h2(v1, v0);
                }
            }
        } else {
            float* dst = Cg + (size_t)m*EMB;
            #pragma unroll
            for (int nt=0; nt<4; nt++){
                const int n = bn + wn*32 + nt*8 + lc*2;
                *(float2*)&dst[n] = make_float2(acc[mt][nt][hf*2] + bias0[nt],
                                                acc[mt][nt][hf*2+1] + bias1[nt]);
            }
        }
    }
}

// ===========================================================================
// Flash attention (fp16): 256 thr, q-tile 128 (warp=16 rows), k-chunk 64.
// 4-stage KV ring, prefetch 3. V row-major [t][d], PV B-frags via ldsm.trans.
// SMEM: Q@0 (18432 B); stage st @ 18432+st*18432: K 64x72h (9216 B) +
//   V 64x72h (9216 B).  Total 18432*5 = 92160 B -> 2 CTAs/SM.
// ===========================================================================
#define FA_SMEM_BYTES (5*18432)

__global__ __launch_bounds__(256, 2)
void flash_attn_k()
{
    constexpr int NC = TGT/64;          // 32 chunks
    extern __shared__ char smc[];
    const uint32_t sb = smem_u32(smc);
    const int tid = threadIdx.x, lane = tid & 31, w = tid >> 5;
    const int lr = lane >> 2, lc = lane & 3;
    const int qt = blockIdx.x, bh = blockIdx.y;
    const int b = bh >> 4, h = bh & 15;
    const int qbase = qt * 128;

    const __half* Qg = g_Qh + (size_t)bh*TGT*HD;
    const __half* Kg = g_Kh + (size_t)bh*TGT*HD;
    const __half* Vg = g_Vh + (size_t)bh*TGT*HD;

    const uint32_t qoff = LDSM_H_A(lane, w*16, 72);
    const uint32_t koff = LDSM_H_B(lane, 0, 72);
    const uint32_t voff = LDSM_H_A(lane, 0, 72);    // trans: A-style addressing

    auto issue_kv = [&](int kc){
        const int st = kc & 3;
        const uint32_t kb = sb + 18432 + st*18432;
        const uint32_t vb = kb + 9216;
        #pragma unroll
        for (int i=0;i<2;i++){   // K,V: 64 rows x 64 halfs each
            int fi = tid + i*256, r = fi>>3, c8 = fi&7;
            cpa16(kb + (r*72 + c8*8)*2, Kg + (size_t)(kc*64+r)*HD + c8*8);
            cpa16(vb + (r*72 + c8*8)*2, Vg + (size_t)(kc*64+r)*HD + c8*8);
        }
        CP_COMMIT();
    };

    // prologue: group0 = Q + KV0; then KV1, KV2
    #pragma unroll
    for (int i=0;i<4;i++){
        int fi = tid + i*256, r = fi>>3, c8 = fi&7;
        cpa16(sb + (r*72 + c8*8)*2, Qg + (size_t)(qbase+r)*HD + c8*8);
    }
    {
        const uint32_t kb = sb + 18432, vb = kb + 9216;
        #pragma unroll
        for (int i=0;i<2;i++){
            int fi = tid + i*256, r = fi>>3, c8 = fi&7;
            cpa16(kb + (r*72 + c8*8)*2, Kg + (size_t)r*HD + c8*8);
            cpa16(vb + (r*72 + c8*8)*2, Vg + (size_t)r*HD + c8*8);
        }
        CP_COMMIT();
    }
    issue_kv(1); issue_kv(2);

    float acc_o[8][4];
    #pragma unroll
    for (int j=0;j<8;j++) for (int k=0;k<4;k++) acc_o[j][k]=0.f;
    float m_r[2] = {-1e30f,-1e30f};
    float l_r[2] = {0.f,0.f};

    const unsigned FULL = 0xffffffffu;

    for (int kc = 0; kc < NC; kc++) {
        if (kc + 2 < NC)      { CP_WAIT(2); }
        else if (kc + 1 < NC) { CP_WAIT(1); }
        else                  { CP_WAIT(0); }
        __syncthreads();
        if (kc + 3 < NC) issue_kv(kc + 3);

        const int st = kc & 3;
        const uint32_t KBu = sb + 18432 + st*18432;
        const uint32_t VBu = KBu + 9216;

        // S = Q K^T  (128q x 64k chunk)
        float s[8][4];
        #pragma unroll
        for (int j=0;j<8;j++) for (int k=0;k<4;k++) s[j][k]=0.f;
        #pragma unroll
        for (int ks=0; ks<4; ks++){
            uint32_t a[4], bf[8][2];
            ldsm4(a[0], a[1], a[2], a[3], sb + (qoff + ks*16)*2);
            #pragma unroll
            for (int p=0; p<4; p++)
                ldsm4(bf[2*p][0], bf[2*p][1], bf[2*p+1][0], bf[2*p+1][1],
                      KBu + (koff + p*16*72 + ks*16)*2);
            #pragma unroll
            for (int nt=0; nt<8; nt++)
                mma16h(s[nt], a, bf[nt]);
        }

        // online softmax over this 64-col chunk
        #pragma unroll
        for (int hf=0; hf<2; hf++){
            float cm = -1e30f;
            #pragma unroll
            for (int nt=0; nt<8; nt++)
                cm = fmaxf(cm, fmaxf(s[nt][hf*2], s[nt][hf*2+1]));
            cm = fmaxf(cm, __shfl_xor_sync(FULL, cm, 1));
            cm = fmaxf(cm, __shfl_xor_sync(FULL, cm, 2));
            const float mn = fmaxf(m_r[hf], cm);
            const float sc = __expf(m_r[hf] - mn);
            float cs = 0.f;
            #pragma unroll
            for (int nt=0; nt<8; nt++){
                float e0 = __expf(s[nt][hf*2]   - mn);
                float e1 = __expf(s[nt][hf*2+1] - mn);
                s[nt][hf*2] = e0; s[nt][hf*2+1] = e1;
                cs += e0 + e1;
            }
            cs += __shfl_xor_sync(FULL, cs, 1);
            cs += __shfl_xor_sync(FULL, cs, 2);
            l_r[hf] = l_r[hf]*sc + cs;
            m_r[hf] = mn;
            #pragma unroll
            for (int nt=0; nt<8; nt++){
                acc_o[nt][hf*2]   *= sc;
                acc_o[nt][hf*2+1] *= sc;
            }
        }

        // O += P V : A-frags packed from S; B-frags via ldmatrix.trans on [t][d]
        #pragma unroll
        for (int ks2=0; ks2<4; ks2++){
            uint32_t a[4];
            a[0] = pack_h2(s[2*ks2  ][1], s[2*ks2  ][0]);
            a[1] = pack_h2(s[2*ks2  ][3], s[2*ks2  ][2]);
            a[2] = pack_h2(s[2*ks2+1][1], s[2*ks2+1][0]);
            a[3] = pack_h2(s[2*ks2+1][3], s[2*ks2+1][2]);
            #pragma unroll
            for (int p=0; p<4; p++){
                uint32_t b0, b1, b2, b3;
                ldsm4t(b0, b1, b2, b3, VBu + (voff + ks2*16*72 + p*16)*2);
                uint32_t bA[2] = {b0, b1}, bB[2] = {b2, b3};
                mma16h(acc_o[2*p  ], a, bA);
                mma16h(acc_o[2*p+1], a, bB);
            }
        }
    }

    #pragma unroll
    for (int hf=0; hf<2; hf++){
        const float invl = 1.0f / l_r[hf];
        const int q = qbase + w*16 + hf*8 + lr;
        __half* dst = g_attnh + ((size_t)q*NBSZ + b)*EMB + h*HD;
        #pragma unroll
        for (int nt=0; nt<8; nt++)
            *(uint32_t*)&dst[nt*8 + lc*2] =
                pack_h2(acc_o[nt][hf*2+1]*invl, acc_o[nt][hf*2]*invl);
        if (lc == 0)
            g_stats[(size_t)bh*TGT + q] = make_float2(m_r[hf], invl);
    }
}

// ===========================================================================
// avg weights (fp16 S): 256 thr, block 128(q) x 64(k), warp 32x32, 2-stage.
// (unchanged — validated round 13)
// ===========================================================================
#define AVG_SMEM_BYTES (2*13824*2)   // 55296

__global__ __launch_bounds__(256, 2)
void avg_attn_k(float* __restrict__ avg_out)
{
    extern __shared__ char smc[];
    const uint32_t sb = smem_u32(smc);
    const int tid = threadIdx.x, lane = tid & 31, wid = tid >> 5;
    const int wm = wid & 3, wn = wid >> 2;          // 4(q) x 2(k)
    const int lr = lane >> 2, lc = lane & 3;
    const int kt = blockIdx.x, qt = blockIdx.y, b = blockIdx.z;

    const uint32_t aoff = LDSM_H_A(lane, wm*32, 72);
    const uint32_t boff = LDSM_H_B(lane, wn*32, 72);

    auto issue_qk = [&](int h){
        const int st = h & 1;
        const int bh = b*NH + h;
        const __half* Qg = g_Qh + (size_t)bh*TGT*HD;
        const __half* Kg = g_Kh + (size_t)bh*TGT*HD;
        const uint32_t qb = sb + st*27648;
        const uint32_t kb = qb + 18432;
        #pragma unroll
        for (int i=0;i<4;i++){
            int fi = tid + i*256, r = fi>>3, c8 = fi&7;
            cpa16(qb + (r*72 + c8*8)*2, Qg + (size_t)(qt*128+r)*HD + c8*8);
        }
        #pragma unroll
        for (int i=0;i<2;i++){
            int fi = tid + i*256, r = fi>>3, c8 = fi&7;
            cpa16(kb + (r*72 + c8*8)*2, Kg + (size_t)(kt*64+r)*HD + c8*8);
        }
        CP_COMMIT();
    };

    float acc[2][4][4];
    #pragma unroll
    for (int i=0;i<2;i++) for (int j=0;j<4;j++) for (int k=0;k<4;k++) acc[i][j][k]=0.f;

    issue_qk(0);
    for (int h = 0; h < NH; h++) {
        CP_WAIT(0);
        __syncthreads();
        if (h + 1 < NH) issue_qk(h+1);
        const int st = h & 1;
        const uint32_t QBu = sb + st*27648;
        const uint32_t KBu = QBu + 18432;

        const int bh = b*NH + h;
        float crow[2][2];
        #pragma unroll
        for (int mt=0; mt<2; mt++)
        #pragma unroll
        for (int hf=0; hf<2; hf++){
            const int q = qt*128 + wm*32 + mt*16 + hf*8 + lr;
            const float2 st2 = g_stats[(size_t)bh*TGT + q];
            crow[mt][hf] = __log2f(st2.y) - st2.x * L2E;
        }

        float s[2][4][4];
        #pragma unroll
        for (int i=0;i<2;i++) for (int j=0;j<4;j++) for (int k=0;k<4;k++) s[i][j][k]=0.f;
        #pragma unroll
        for (int ks=0; ks<4; ks++){
            uint32_t af[2][4], bf[4][2];
            #pragma unroll
            for (int mt=0; mt<2; mt++)
                ldsm4(af[mt][0], af[mt][1], af[mt][2], af[mt][3],
                      QBu + (aoff + mt*16*72 + ks*16)*2);
            #pragma unroll
            for (int p=0; p<2; p++)
                ldsm4(bf[2*p][0], bf[2*p][1], bf[2*p+1][0], bf[2*p+1][1],
                      KBu + (boff + p*16*72 + ks*16)*2);
            #pragma unroll
            for (int mt=0; mt<2; mt++)
                #pragma unroll
                for (int nt=0; nt<4; nt++)
                    mma16h(s[mt][nt], af[mt], bf[nt]);
        }

        #pragma unroll
        for (int mt=0; mt<2; mt++)
        #pragma unroll
        for (int hf=0; hf<2; hf++){
            const float c = crow[mt][hf];
            #pragma unroll
            for (int nt=0; nt<4; nt++){
                acc[mt][nt][hf*2]   += exp2f(fmaf(s[mt][nt][hf*2],   L2E, c));
                acc[mt][nt][hf*2+1] += exp2f(fmaf(s[mt][nt][hf*2+1], L2E, c));
            }
        }
    }

    const float invH = 1.0f / NH;
    #pragma unroll
    for (int mt=0; mt<2; mt++)
    #pragma unroll
    for (int hf=0; hf<2; hf++){
        const int q = qt*128 + wm*32 + mt*16 + hf*8 + lr;
        float* dst = avg_out + ((size_t)b*TGT + q)*TGT + kt*64 + wn*32;
        #pragma unroll
        for (int nt=0; nt<4; nt++)
            *(float2*)(dst + nt*8 + lc*2) =
                make_float2(acc[mt][nt][hf*2]*invH, acc[mt][nt][hf*2+1]*invH);
    }
}

// ---------------------------------------------------------------------------
extern "C" void kernel_launch(void* const* d_in, const int* in_sizes, int n_in,
                              void* d_out, int out_size)
{
    const float* query = (const float*)d_in[0];
    const float* w_in  = (const float*)d_in[1];
    const float* b_in  = (const float*)d_in[2];
    const float* w_out = (const float*)d_in[3];
    const float* b_out = (const float*)d_in[4];

    float* out      = (float*)d_out;
    float* attn_out = out;                           // [T,B,E]
    float* avg_out  = out + (size_t)TGT*NBSZ*EMB;    // [B,T,T]

    cudaFuncSetAttribute(mma_gemm<0>,  cudaFuncAttributeMaxDynamicSharedMemorySize, GEMM_SMEM_BYTES);
    cudaFuncSetAttribute(mma_gemm<3>,  cudaFuncAttributeMaxDynamicSharedMemorySize, GEMM_SMEM_BYTES);
    cudaFuncSetAttribute(flash_attn_k, cudaFuncAttributeMaxDynamicSharedMemorySize, FA_SMEM_BYTES);
    cudaFuncSetAttribute(avg_attn_k,   cudaFuncAttributeMaxDynamicSharedMemorySize, AVG_SMEM_BYTES);

    __half* d_qh;  cudaGetSymbolAddress((void**)&d_qh,  g_qh);
    __half* d_wih; cudaGetSymbolAddress((void**)&d_wih, g_wih);
    __half* d_woh; cudaGetSymbolAddress((void**)&d_woh, g_woh);

    // 0. fp32 -> fp16 convert (single launch)
    {
        int total = MROWS*EMB/4 + 3*EMB*EMB/4 + EMB*EMB/4;
        preconv_all_k<<<(total+255)/256, 256>>>(
            (const float4*)query, (const float4*)w_in, (const float4*)w_out,
            (uint2*)d_qh, (uint2*)d_wih, (uint2*)d_woh);
    }

    // 1. QKV projection (fp16, all outputs row-major)
    mma_gemm<0><<<dim3(3*EMB/128, MROWS/128), 256, GEMM_SMEM_BYTES>>>(nullptr, b_in);

    // 2. Flash attention (64-wide chunks, trans-ldmatrix V)
    flash_attn_k<<<dim3(TGT/128, NBH), 256, FA_SMEM_BYTES>>>();

    // 3. Averaged attention weights
    avg_attn_k<<<dim3(TGT/64, TGT/128, NBSZ), 256, AVG_SMEM_BYTES>>>(avg_out);

    // 4. Output projection (fp16 in, fp32 out)
    mma_gemm<3><<<dim3(EMB/128, MROWS/128), 256, GEMM_SMEM_BYTES>>>(attn_out, b_out);
}

// round 15
// speedup vs baseline: 2.2059x; 1.0236x over previous
#include <cuda_runtime.h>
#include <cuda_fp16.h>
#include <cstdint>
#include <math.h>

#define TGT   2048
#define NBSZ  2
#define EMB   1024
#define NH    16
#define HD    64
#define NBH   (NBSZ*NH)      // 32
#define MROWS (TGT*NBSZ)     // 4096

// ---------------- scratch (device globals, all fp16 operands) ---------------
static __device__ __half g_Qh [(size_t)NBH*TGT*HD];     // pre-scaled
static __device__ __half g_Kh [(size_t)NBH*TGT*HD];
static __device__ __half g_Vh [(size_t)NBH*TGT*HD];     // [bh][t][d] row-major
static __device__ __half g_attnh[(size_t)MROWS*EMB];
static __device__ float2 g_stats[(size_t)NBH*TGT];      // (rowmax, 1/rowsum)
static __device__ __half g_qh [(size_t)MROWS*EMB];
static __device__ __half g_wih[(size_t)3*EMB*EMB];
static __device__ __half g_woh[(size_t)EMB*EMB];

// ---------------- helpers ---------------------------------------------------
__device__ __forceinline__ uint32_t pack_h2(float hi, float lo){
    uint32_t r; asm("cvt.rn.f16x2.f32 %0, %1, %2;" : "=r"(r) : "f"(hi), "f"(lo));
    return r;
}
__device__ __forceinline__ void mma16h(float* c, const uint32_t* a, const uint32_t* b){
    asm volatile("mma.sync.aligned.m16n8k16.row.col.f32.f16.f16.f32 "
        "{%0,%1,%2,%3}, {%4,%5,%6,%7}, {%8,%9}, {%0,%1,%2,%3};"
        : "+f"(c[0]), "+f"(c[1]), "+f"(c[2]), "+f"(c[3])
        : "r"(a[0]), "r"(a[1]), "r"(a[2]), "r"(a[3]), "r"(b[0]), "r"(b[1]));
}
__device__ __forceinline__ void ldsm4(uint32_t& r0, uint32_t& r1, uint32_t& r2,
                                      uint32_t& r3, uint32_t addr){
    asm volatile("ldmatrix.sync.aligned.m8n8.x4.shared.b16 {%0,%1,%2,%3}, [%4];"
        : "=r"(r0), "=r"(r1), "=r"(r2), "=r"(r3) : "r"(addr));
}
__device__ __forceinline__ void ldsm4t(uint32_t& r0, uint32_t& r1, uint32_t& r2,
                                       uint32_t& r3, uint32_t addr){
    asm volatile("ldmatrix.sync.aligned.m8n8.x4.trans.shared.b16 {%0,%1,%2,%3}, [%4];"
        : "=r"(r0), "=r"(r1), "=r"(r2), "=r"(r3) : "r"(addr));
}
__device__ __forceinline__ uint32_t smem_u32(const void* p){
    uint32_t a; asm("{ .reg .u64 t; cvta.to.shared.u64 t, %1; cvt.u32.u64 %0, t; }":"=r"(a):"l"(p));
    return a;
}
__device__ __forceinline__ void cpa16(uint32_t s, const void* g){
    asm volatile("cp.async.cg.shared.global [%0], [%1], 16;" :: "r"(s), "l"(g) : "memory");
}
#define CP_COMMIT() asm volatile("cp.async.commit_group;" ::: "memory")
#define CP_WAIT(n)  asm volatile("cp.async.wait_group %0;" :: "n"(n) : "memory")

// fp16 ldmatrix lane->offset (in HALFS) for m16n8k16 fragments.
#define LDSM_H_A(j, rowbase, stride) \
    ((((rowbase) + (((j)>>3)&1)*8 + ((j)&7))*(stride)) + (((j)>>4)*8))
#define LDSM_H_B(j, rowbase, stride) \
    ((((rowbase) + (((j)>>4)*8) + ((j)&7))*(stride)) + ((((j)>>3)&1)*8))

#define L2E 1.4426950408889634f

// ---------------- fused pre-convert fp32 -> fp16 (one launch) ---------------
__global__ void preconv_all_k(const float4* __restrict__ q,
                              const float4* __restrict__ wi,
                              const float4* __restrict__ wo,
                              uint2* __restrict__ dq,
                              uint2* __restrict__ dwi,
                              uint2* __restrict__ dwo)
{
    const int NQ = MROWS*EMB/4, NWI = 3*EMB*EMB/4, NWO = EMB*EMB/4;
    int i = blockIdx.x*blockDim.x + threadIdx.x;
    float4 v; uint2 o;
    if (i < NQ)              { v = q[i];        o.x = pack_h2(v.y, v.x); o.y = pack_h2(v.w, v.z); dq[i] = o; }
    else if (i < NQ+NWI)     { v = wi[i-NQ];    o.x = pack_h2(v.y, v.x); o.y = pack_h2(v.w, v.z); dwi[i-NQ] = o; }
    else if (i < NQ+NWI+NWO) { v = wo[i-NQ-NWI];o.x = pack_h2(v.y, v.x); o.y = pack_h2(v.w, v.z); dwo[i-NQ-NWI] = o; }
}

// ===========================================================================
// QKV GEMM (fp16): block 128x128, 256 thr, warp 64x32, BK=64, 3-stage ring.
// SMEM halfs: stage st @ st*18432 B: A (128x72) + B (128x72). 110592 B.
// ===========================================================================
#define GEMM_SMEM_BYTES (3*18432*2)   // 110592

__global__ __launch_bounds__(256, 2)
void qkv_gemm(const float* __restrict__ biasg)
{
    constexpr int KC = 16;
    extern __shared__ char smc[];
    const uint32_t sb = smem_u32(smc);
    const int tid = threadIdx.x, lane = tid & 31, wid = tid >> 5;
    const int wm = wid & 1, wn = wid >> 1;
    const int lr = lane >> 2, lc = lane & 3;
    const int bm = blockIdx.y * 128, bn = blockIdx.x * 128;

    const __half* A = g_qh;
    const __half* B = g_wih;

    const uint32_t aoff = LDSM_H_A(lane, wm*64, 72);
    const uint32_t boff = LDSM_H_B(lane, wn*32, 72);

    float acc[4][4][4];
    #pragma unroll
    for (int i=0;i<4;i++) for (int j=0;j<4;j++) for (int k=0;k<4;k++) acc[i][j][k]=0.f;

    auto issue = [&](int c){
        const int k0 = c*64, st = c % 3;
        const uint32_t ab = sb + st*36864;
        const uint32_t bb = ab + 18432;
        #pragma unroll
        for (int i=0;i<4;i++){
            int fi = tid + i*256, r = fi>>3, c8 = fi&7;
            cpa16(ab + (r*72 + c8*8)*2, A + (size_t)(bm+r)*EMB + k0 + c8*8);
            cpa16(bb + (r*72 + c8*8)*2, B + (size_t)(bn+r)*EMB + k0 + c8*8);
        }
        CP_COMMIT();
    };

    issue(0); issue(1);
    for (int c = 0; c < KC; c++) {
        if (c + 1 < KC) { CP_WAIT(1); } else { CP_WAIT(0); }
        __syncthreads();
        if (c + 2 < KC) issue(c+2);
        const int st = c % 3;
        const uint32_t Ab = sb + st*36864;
        const uint32_t Bb = Ab + 18432;
        #pragma unroll
        for (int ks = 0; ks < 4; ks++) {
            uint32_t af[4][4], bf[4][2];
            #pragma unroll
            for (int mt=0; mt<4; mt++)
                ldsm4(af[mt][0], af[mt][1], af[mt][2], af[mt][3],
                      Ab + (aoff + mt*16*72 + ks*16)*2);
            #pragma unroll
            for (int p=0; p<2; p++)
                ldsm4(bf[2*p][0], bf[2*p][1], bf[2*p+1][0], bf[2*p+1][1],
                      Bb + (boff + p*16*72 + ks*16)*2);
            #pragma unroll
            for (int mt=0; mt<4; mt++)
                #pragma unroll
                for (int nt=0; nt<4; nt++)
                    mma16h(acc[mt][nt], af[mt], bf[nt]);
        }
    }

    float bias0[4], bias1[4];
    #pragma unroll
    for (int nt=0; nt<4; nt++){
        int n = bn + wn*32 + nt*8 + lc*2;
        bias0[nt] = biasg[n]; bias1[nt] = biasg[n+1];
    }

    #pragma unroll
    for (int mt=0; mt<4; mt++)
    #pragma unroll
    for (int hf=0; hf<2; hf++){
        const int m = bm + wm*64 + mt*16 + hf*8 + lr;
        const int t = m >> 1, b = m & 1;
        #pragma unroll
        for (int nt=0; nt<4; nt++){
            const int n = bn + wn*32 + nt*8 + lc*2;
            float v0 = acc[mt][nt][hf*2+0] + bias0[nt];
            float v1 = acc[mt][nt][hf*2+1] + bias1[nt];
            const int which = n >> 10, e = n & 1023, h = e >> 6, d = e & 63;
            const int bh = b*NH + h;
            if (which == 0) {
                *(uint32_t*)&g_Qh[((size_t)bh*TGT + t)*HD + d] =
                    pack_h2(v1*0.125f, v0*0.125f);
            } else if (which == 1) {
                *(uint32_t*)&g_Kh[((size_t)bh*TGT + t)*HD + d] = pack_h2(v1, v0);
            } else {
                *(uint32_t*)&g_Vh[((size_t)bh*TGT + t)*HD + d] = pack_h2(v1, v0);
            }
        }
    }
}

// ===========================================================================
// Flash attention (fp16): unchanged from round 14 (validated).
// ===========================================================================
#define FA_SMEM_BYTES (5*18432)

__global__ __launch_bounds__(256, 2)
void flash_attn_k()
{
    constexpr int NC = TGT/64;
    extern __shared__ char smc[];
    const uint32_t sb = smem_u32(smc);
    const int tid = threadIdx.x, lane = tid & 31, w = tid >> 5;
    const int lr = lane >> 2, lc = lane & 3;
    const int qt = blockIdx.x, bh = blockIdx.y;
    const int b = bh >> 4, h = bh & 15;
    const int qbase = qt * 128;

    const __half* Qg = g_Qh + (size_t)bh*TGT*HD;
    const __half* Kg = g_Kh + (size_t)bh*TGT*HD;
    const __half* Vg = g_Vh + (size_t)bh*TGT*HD;

    const uint32_t qoff = LDSM_H_A(lane, w*16, 72);
    const uint32_t koff = LDSM_H_B(lane, 0, 72);
    const uint32_t voff = LDSM_H_A(lane, 0, 72);

    auto issue_kv = [&](int kc){
        const int st = kc & 3;
        const uint32_t kb = sb + 18432 + st*18432;
        const uint32_t vb = kb + 9216;
        #pragma unroll
        for (int i=0;i<2;i++){
            int fi = tid + i*256, r = fi>>3, c8 = fi&7;
            cpa16(kb + (r*72 + c8*8)*2, Kg + (size_t)(kc*64+r)*HD + c8*8);
            cpa16(vb + (r*72 + c8*8)*2, Vg + (size_t)(kc*64+r)*HD + c8*8);
        }
        CP_COMMIT();
    };

    #pragma unroll
    for (int i=0;i<4;i++){
        int fi = tid + i*256, r = fi>>3, c8 = fi&7;
        cpa16(sb + (r*72 + c8*8)*2, Qg + (size_t)(qbase+r)*HD + c8*8);
    }
    {
        const uint32_t kb = sb + 18432, vb = kb + 9216;
        #pragma unroll
        for (int i=0;i<2;i++){
            int fi = tid + i*256, r = fi>>3, c8 = fi&7;
            cpa16(kb + (r*72 + c8*8)*2, Kg + (size_t)r*HD + c8*8);
            cpa16(vb + (r*72 + c8*8)*2, Vg + (size_t)r*HD + c8*8);
        }
        CP_COMMIT();
    }
    issue_kv(1); issue_kv(2);

    float acc_o[8][4];
    #pragma unroll
    for (int j=0;j<8;j++) for (int k=0;k<4;k++) acc_o[j][k]=0.f;
    float m_r[2] = {-1e30f,-1e30f};
    float l_r[2] = {0.f,0.f};

    const unsigned FULL = 0xffffffffu;

    for (int kc = 0; kc < NC; kc++) {
        if (kc + 2 < NC)      { CP_WAIT(2); }
        else if (kc + 1 < NC) { CP_WAIT(1); }
        else                  { CP_WAIT(0); }
        __syncthreads();
        if (kc + 3 < NC) issue_kv(kc + 3);

        const int st = kc & 3;
        const uint32_t KBu = sb + 18432 + st*18432;
        const uint32_t VBu = KBu + 9216;

        float s[8][4];
        #pragma unroll
        for (int j=0;j<8;j++) for (int k=0;k<4;k++) s[j][k]=0.f;
        #pragma unroll
        for (int ks=0; ks<4; ks++){
            uint32_t a[4], bf[8][2];
            ldsm4(a[0], a[1], a[2], a[3], sb + (qoff + ks*16)*2);
            #pragma unroll
            for (int p=0; p<4; p++)
                ldsm4(bf[2*p][0], bf[2*p][1], bf[2*p+1][0], bf[2*p+1][1],
                      KBu + (koff + p*16*72 + ks*16)*2);
            #pragma unroll
            for (int nt=0; nt<8; nt++)
                mma16h(s[nt], a, bf[nt]);
        }

        #pragma unroll
        for (int hf=0; hf<2; hf++){
            float cm = -1e30f;
            #pragma unroll
            for (int nt=0; nt<8; nt++)
                cm = fmaxf(cm, fmaxf(s[nt][hf*2], s[nt][hf*2+1]));
            cm = fmaxf(cm, __shfl_xor_sync(FULL, cm, 1));
            cm = fmaxf(cm, __shfl_xor_sync(FULL, cm, 2));
            const float mn = fmaxf(m_r[hf], cm);
            const float sc = __expf(m_r[hf] - mn);
            float cs = 0.f;
            #pragma unroll
            for (int nt=0; nt<8; nt++){
                float e0 = __expf(s[nt][hf*2]   - mn);
                float e1 = __expf(s[nt][hf*2+1] - mn);
                s[nt][hf*2] = e0; s[nt][hf*2+1] = e1;
                cs += e0 + e1;
            }
            cs += __shfl_xor_sync(FULL, cs, 1);
            cs += __shfl_xor_sync(FULL, cs, 2);
            l_r[hf] = l_r[hf]*sc + cs;
            m_r[hf] = mn;
            #pragma unroll
            for (int nt=0; nt<8; nt++){
                acc_o[nt][hf*2]   *= sc;
                acc_o[nt][hf*2+1] *= sc;
            }
        }

        #pragma unroll
        for (int ks2=0; ks2<4; ks2++){
            uint32_t a[4];
            a[0] = pack_h2(s[2*ks2  ][1], s[2*ks2  ][0]);
            a[1] = pack_h2(s[2*ks2  ][3], s[2*ks2  ][2]);
            a[2] = pack_h2(s[2*ks2+1][1], s[2*ks2+1][0]);
            a[3] = pack_h2(s[2*ks2+1][3], s[2*ks2+1][2]);
            #pragma unroll
            for (int p=0; p<4; p++){
                uint32_t b0, b1, b2, b3;
                ldsm4t(b0, b1, b2, b3, VBu + (voff + ks2*16*72 + p*16)*2);
                uint32_t bA[2] = {b0, b1}, bB[2] = {b2, b3};
                mma16h(acc_o[2*p  ], a, bA);
                mma16h(acc_o[2*p+1], a, bB);
            }
        }
    }

    #pragma unroll
    for (int hf=0; hf<2; hf++){
        const float invl = 1.0f / l_r[hf];
        const int q = qbase + w*16 + hf*8 + lr;
        __half* dst = g_attnh + ((size_t)q*NBSZ + b)*EMB + h*HD;
        #pragma unroll
        for (int nt=0; nt<8; nt++)
            *(uint32_t*)&dst[nt*8 + lc*2] =
                pack_h2(acc_o[nt][hf*2+1]*invl, acc_o[nt][hf*2]*invl);
        if (lc == 0)
            g_stats[(size_t)bh*TGT + q] = make_float2(m_r[hf], invl);
    }
}

// ===========================================================================
// Merged tail kernel: blocks [0,1024) = avg weights; [1024,1280) = out-proj.
// Both depend only on flash; they execute concurrently in one launch.
// Bodies are verbatim round-14 validated code. SMEM request = 110592 B
// (out-proj's 3-stage ring); both paths keep 2 CTAs/SM.
// ===========================================================================
#define TAIL_SMEM_BYTES (3*18432*2)   // 110592

__device__ __forceinline__ void avg_body(float* __restrict__ avg_out, int bid)
{
    extern __shared__ char smc[];
    const uint32_t sb = smem_u32(smc);
    const int tid = threadIdx.x, lane = tid & 31, wid = tid >> 5;
    const int wm = wid & 3, wn = wid >> 2;
    const int lr = lane >> 2, lc = lane & 3;
    const int kt = bid & 31, qt = (bid >> 5) & 15, b = bid >> 9;

    const uint32_t aoff = LDSM_H_A(lane, wm*32, 72);
    const uint32_t boff = LDSM_H_B(lane, wn*32, 72);

    auto issue_qk = [&](int h){
        const int st = h & 1;
        const int bh = b*NH + h;
        const __half* Qg = g_Qh + (size_t)bh*TGT*HD;
        const __half* Kg = g_Kh + (size_t)bh*TGT*HD;
        const uint32_t qb = sb + st*27648;
        const uint32_t kb = qb + 18432;
        #pragma unroll
        for (int i=0;i<4;i++){
            int fi = tid + i*256, r = fi>>3, c8 = fi&7;
            cpa16(qb + (r*72 + c8*8)*2, Qg + (size_t)(qt*128+r)*HD + c8*8);
        }
        #pragma unroll
        for (int i=0;i<2;i++){
            int fi = tid + i*256, r = fi>>3, c8 = fi&7;
            cpa16(kb + (r*72 + c8*8)*2, Kg + (size_t)(kt*64+r)*HD + c8*8);
        }
        CP_COMMIT();
    };

    float acc[2][4][4];
    #pragma unroll
    for (int i=0;i<2;i++) for (int j=0;j<4;j++) for (int k=0;k<4;k++) acc[i][j][k]=0.f;

    issue_qk(0);
    for (int h = 0; h < NH; h++) {
        CP_WAIT(0);
        __syncthreads();
        if (h + 1 < NH) issue_qk(h+1);
        const int st = h & 1;
        const uint32_t QBu = sb + st*27648;
        const uint32_t KBu = QBu + 18432;

        const int bh = b*NH + h;
        float crow[2][2];
        #pragma unroll
        for (int mt=0; mt<2; mt++)
        #pragma unroll
        for (int hf=0; hf<2; hf++){
            const int q = qt*128 + wm*32 + mt*16 + hf*8 + lr;
            const float2 st2 = g_stats[(size_t)bh*TGT + q];
            crow[mt][hf] = __log2f(st2.y) - st2.x * L2E;
        }

        float s[2][4][4];
        #pragma unroll
        for (int i=0;i<2;i++) for (int j=0;j<4;j++) for (int k=0;k<4;k++) s[i][j][k]=0.f;
        #pragma unroll
        for (int ks=0; ks<4; ks++){
            uint32_t af[2][4], bf[4][2];
            #pragma unroll
            for (int mt=0; mt<2; mt++)
                ldsm4(af[mt][0], af[mt][1], af[mt][2], af[mt][3],
                      QBu + (aoff + mt*16*72 + ks*16)*2);
            #pragma unroll
            for (int p=0; p<2; p++)
                ldsm4(bf[2*p][0], bf[2*p][1], bf[2*p+1][0], bf[2*p+1][1],
                      KBu + (boff + p*16*72 + ks*16)*2);
            #pragma unroll
            for (int mt=0; mt<2; mt++)
                #pragma unroll
                for (int nt=0; nt<4; nt++)
                    mma16h(s[mt][nt], af[mt], bf[nt]);
        }

        #pragma unroll
        for (int mt=0; mt<2; mt++)
        #pragma unroll
        for (int hf=0; hf<2; hf++){
            const float c = crow[mt][hf];
            #pragma unroll
            for (int nt=0; nt<4; nt++){
                acc[mt][nt][hf*2]   += exp2f(fmaf(s[mt][nt][hf*2],   L2E, c));
                acc[mt][nt][hf*2+1] += exp2f(fmaf(s[mt][nt][hf*2+1], L2E, c));
            }
        }
    }

    const float invH = 1.0f / NH;
    #pragma unroll
    for (int mt=0; mt<2; mt++)
    #pragma unroll
    for (int hf=0; hf<2; hf++){
        const int q = qt*128 + wm*32 + mt*16 + hf*8 + lr;
        float* dst = avg_out + ((size_t)b*TGT + q)*TGT + kt*64 + wn*32;
        #pragma unroll
        for (int nt=0; nt<4; nt++)
            *(float2*)(dst + nt*8 + lc*2) =
                make_float2(acc[mt][nt][hf*2]*invH, acc[mt][nt][hf*2+1]*invH);
    }
}

__device__ __forceinline__ void outproj_body(float* __restrict__ Cg,
                                             const float* __restrict__ biasg, int bid)
{
    constexpr int KC = 16;
    extern __shared__ char smc[];
    const uint32_t sb = smem_u32(smc);
    const int tid = threadIdx.x, lane = tid & 31, wid = tid >> 5;
    const int wm = wid & 1, wn = wid >> 1;
    const int lr = lane >> 2, lc = lane & 3;
    const int bm = (bid >> 3) * 128, bn = (bid & 7) * 128;

    const __half* A = g_attnh;
    const __half* B = g_woh;

    const uint32_t aoff = LDSM_H_A(lane, wm*64, 72);
    const uint32_t boff = LDSM_H_B(lane, wn*32, 72);

    float acc[4][4][4];
    #pragma unroll
    for (int i=0;i<4;i++) for (int j=0;j<4;j++) for (int k=0;k<4;k++) acc[i][j][k]=0.f;

    auto issue = [&](int c){
        const int k0 = c*64, st = c % 3;
        const uint32_t ab = sb + st*36864;
        const uint32_t bb = ab + 18432;
        #pragma unroll
        for (int i=0;i<4;i++){
            int fi = tid + i*256, r = fi>>3, c8 = fi&7;
            cpa16(ab + (r*72 + c8*8)*2, A + (size_t)(bm+r)*EMB + k0 + c8*8);
            cpa16(bb + (r*72 + c8*8)*2, B + (size_t)(bn+r)*EMB + k0 + c8*8);
        }
        CP_COMMIT();
    };

    issue(0); issue(1);
    for (int c = 0; c < KC; c++) {
        if (c + 1 < KC) { CP_WAIT(1); } else { CP_WAIT(0); }
        __syncthreads();
        if (c + 2 < KC) issue(c+2);
        const int st = c % 3;
        const uint32_t Ab = sb + st*36864;
        const uint32_t Bb = Ab + 18432;
        #pragma unroll
        for (int ks = 0; ks < 4; ks++) {
            uint32_t af[4][4], bf[4][2];
            #pragma unroll
            for (int mt=0; mt<4; mt++)
                ldsm4(af[mt][0], af[mt][1], af[mt][2], af[mt][3],
                      Ab + (aoff + mt*16*72 + ks*16)*2);
            #pragma unroll
            for (int p=0; p<2; p++)
                ldsm4(bf[2*p][0], bf[2*p][1], bf[2*p+1][0], bf[2*p+1][1],
                      Bb + (boff + p*16*72 + ks*16)*2);
            #pragma unroll
            for (int mt=0; mt<4; mt++)
                #pragma unroll
                for (int nt=0; nt<4; nt++)
                    mma16h(acc[mt][nt], af[mt], bf[nt]);
        }
    }

    float bias0[4], bias1[4];
    #pragma unroll
    for (int nt=0; nt<4; nt++){
        int n = bn + wn*32 + nt*8 + lc*2;
        bias0[nt] = biasg[n]; bias1[nt] = biasg[n+1];
    }

    #pragma unroll
    for (int mt=0; mt<4; mt++)
    #pragma unroll
    for (int hf=0; hf<2; hf++){
        const int m = bm + wm*64 + mt*16 + hf*8 + lr;
        float* dst = Cg + (size_t)m*EMB;
        #pragma unroll
        for (int nt=0; nt<4; nt++){
            const int n = bn + wn*32 + nt*8 + lc*2;
            *(float2*)&dst[n] = make_float2(acc[mt][nt][hf*2] + bias0[nt],
                                            acc[mt][nt][hf*2+1] + bias1[nt]);
        }
    }
}

__global__ __launch_bounds__(256, 2)
void tail_k(float* __restrict__ attn_out, const float* __restrict__ b_out,
            float* __restrict__ avg_out)
{
    const int bid = blockIdx.x;
    if (bid < 1024) avg_body(avg_out, bid);
    else            outproj_body(attn_out, b_out, bid - 1024);
}

// ---------------------------------------------------------------------------
extern "C" void kernel_launch(void* const* d_in, const int* in_sizes, int n_in,
                              void* d_out, int out_size)
{
    const float* query = (const float*)d_in[0];
    const float* w_in  = (const float*)d_in[1];
    const float* b_in  = (const float*)d_in[2];
    const float* w_out = (const float*)d_in[3];
    const float* b_out = (const float*)d_in[4];

    float* out      = (float*)d_out;
    float* attn_out = out;                           // [T,B,E]
    float* avg_out  = out + (size_t)TGT*NBSZ*EMB;    // [B,T,T]

    cudaFuncSetAttribute(qkv_gemm,     cudaFuncAttributeMaxDynamicSharedMemorySize, GEMM_SMEM_BYTES);
    cudaFuncSetAttribute(flash_attn_k, cudaFuncAttributeMaxDynamicSharedMemorySize, FA_SMEM_BYTES);
    cudaFuncSetAttribute(tail_k,       cudaFuncAttributeMaxDynamicSharedMemorySize, TAIL_SMEM_BYTES);

    __half* d_qh;  cudaGetSymbolAddress((void**)&d_qh,  g_qh);
    __half* d_wih; cudaGetSymbolAddress((void**)&d_wih, g_wih);
    __half* d_woh; cudaGetSymbolAddress((void**)&d_woh, g_woh);

    // 0. fp32 -> fp16 convert (single launch)
    {
        int total = MROWS*EMB/4 + 3*EMB*EMB/4 + EMB*EMB/4;
        preconv_all_k<<<(total+255)/256, 256>>>(
            (const float4*)query, (const float4*)w_in, (const float4*)w_out,
            (uint2*)d_qh, (uint2*)d_wih, (uint2*)d_woh);
    }

    // 1. QKV projection
    qkv_gemm<<<dim3(3*EMB/128, MROWS/128), 256, GEMM_SMEM_BYTES>>>(b_in);

    // 2. Flash attention
    flash_attn_k<<<dim3(TGT/128, NBH), 256, FA_SMEM_BYTES>>>();

    // 3. Merged tail: avg weights (blocks 0-1023) || out-projection (1024-1279)
    tail_k<<<1280, 256, TAIL_SMEM_BYTES>>>(attn_out, b_out, avg_out);
}